// round 2
// baseline (speedup 1.0000x reference)
#include <cuda_runtime.h>
#include <math.h>

// ---------------- problem constants ----------------
#define BATCH   8
#define SEQ     1124
#define EMB     1024
#define NHEAD   16
#define HDIM    64
#define NPATCH  1024
#define NQ      100
#define NTOK    (BATCH*SEQ)       // 8992
#define H3      3072
#define FHID    4096
#define ATTNSCALE 0.125f          // 64^-0.5
#define NEG_INF_V (-1000000000.0f)

// ---------------- scratch (static device memory; no allocs; ~367 MB total) ----------------
__device__ float g_xn[(size_t)NTOK*EMB];          // LN output (reused for LN1 and LN2)
__device__ float g_qkv[(size_t)NTOK*H3];          // qkv projections
__device__ float g_attnout[(size_t)NTOK*EMB];     // attention output (heads merged)
__device__ float g_x1[(size_t)NTOK*EMB];          // residual 1 output
__device__ float g_h[(size_t)NTOK*FHID];          // MLP hidden

// ---------------- block reduction (sum, sumsq) ----------------
__device__ __forceinline__ void blockReduce2(float &a, float &b) {
    __shared__ float sa[8], sb[8];
    int lane = threadIdx.x & 31, w = threadIdx.x >> 5;
    #pragma unroll
    for (int o = 16; o; o >>= 1) {
        a += __shfl_xor_sync(0xffffffffu, a, o);
        b += __shfl_xor_sync(0xffffffffu, b, o);
    }
    if (lane == 0) { sa[w] = a; sb[w] = b; }
    __syncthreads();
    if (w == 0) {
        float ra = (lane < 8) ? sa[lane] : 0.f;
        float rb = (lane < 8) ? sb[lane] : 0.f;
        #pragma unroll
        for (int o = 4; o; o >>= 1) {
            ra += __shfl_xor_sync(0xffffffffu, ra, o);
            rb += __shfl_xor_sync(0xffffffffu, rb, o);
        }
        if (lane == 0) { sa[0] = ra; sb[0] = rb; }
    }
    __syncthreads();
    a = sa[0]; b = sb[0];
}

// ---------------- LayerNorm: one block per row (EMB=1024, 256 threads) ----------------
__global__ void ln_kernel(const float* __restrict__ x, const float* __restrict__ g,
                          const float* __restrict__ be, float* __restrict__ out) {
    const int row = blockIdx.x, tid = threadIdx.x;
    const float* xr = x + (size_t)row * EMB;
    float v[4];
    float s = 0.f, sq = 0.f;
    #pragma unroll
    for (int i = 0; i < 4; i++) {
        float t = xr[tid + i * 256];
        v[i] = t; s += t; sq += t * t;
    }
    blockReduce2(s, sq);
    const float m   = s * (1.0f / EMB);
    const float var = sq * (1.0f / EMB) - m * m;
    const float inv = rsqrtf(var + 1e-6f);
    float* orow = out + (size_t)row * EMB;
    #pragma unroll
    for (int i = 0; i < 4; i++) {
        int c = tid + i * 256;
        orow[c] = (v[i] - m) * inv * g[c] + be[c];
    }
}

// ---------------- general fp32 GEMM 128x128x8, 256 threads, 8x8 microtile ----------------
// A: MxK row-major (lda), B: KxN row-major (ldb), C: MxN row-major (ldc).
// Requires N % 128 == 0 (all call sites: 3072/1024/4096). M, K guarded.
// EPI: 0 = none; 1 = +bias +residual; 2 = +bias then exact GELU.
template<int EPI>
__global__ void gemm128(const float* __restrict__ A, int lda,
                        const float* __restrict__ B, int ldb,
                        float* __restrict__ C, int ldc,
                        int M, int N, int K,
                        const float* __restrict__ bias,
                        const float* __restrict__ resid, int ldr) {
    constexpr int BM = 128, BN = 128, BK = 8, TM = 8, TN = 8;
    __shared__ float As[BK][BM + 4];
    __shared__ float Bs[BK][BN];
    const int tid  = threadIdx.x;
    const int trow = tid >> 4;
    const int tcol = tid & 15;
    const int row0 = blockIdx.y * BM;
    const int col0 = blockIdx.x * BN;

    float acc[TM][TN];
    #pragma unroll
    for (int i = 0; i < TM; i++)
        #pragma unroll
        for (int j = 0; j < TN; j++) acc[i][j] = 0.f;

    for (int k0 = 0; k0 < K; k0 += BK) {
        #pragma unroll
        for (int it = 0; it < (BM * BK) / 256; ++it) {
            int idx = tid + it * 256;
            int r = idx >> 3, c = idx & 7;
            int gr = row0 + r, gc = k0 + c;
            As[c][r] = (gr < M && gc < K) ? A[(size_t)gr * lda + gc] : 0.f;
        }
        #pragma unroll
        for (int it = 0; it < (BK * BN) / 256; ++it) {
            int idx = tid + it * 256;
            int r = idx >> 7, c = idx & 127;
            int gr = k0 + r;
            Bs[r][c] = (gr < K) ? B[(size_t)gr * ldb + col0 + c] : 0.f;
        }
        __syncthreads();
        #pragma unroll
        for (int k = 0; k < BK; k++) {
            float a[TM], bv[TN];
            #pragma unroll
            for (int i = 0; i < TM; i++) a[i] = As[k][trow * TM + i];
            #pragma unroll
            for (int j = 0; j < TN; j++) bv[j] = Bs[k][tcol * TN + j];
            #pragma unroll
            for (int i = 0; i < TM; i++)
                #pragma unroll
                for (int j = 0; j < TN; j++) acc[i][j] += a[i] * bv[j];
        }
        __syncthreads();
    }

    #pragma unroll
    for (int i = 0; i < TM; i++) {
        int gr = row0 + trow * TM + i;
        if (gr >= M) continue;
        #pragma unroll
        for (int j = 0; j < TN; j++) {
            int gc = col0 + tcol * TN + j;
            float v = acc[i][j];
            if (EPI >= 1) v += bias[gc];
            if (EPI == 1) v += resid[(size_t)gr * ldr + gc];
            if (EPI == 2) v = 0.5f * v * (1.0f + erff(v * 0.70710678118654752f));
            C[(size_t)gr * ldc + gc] = v;
        }
    }
}

// ---------------- fused flash-style attention ----------------
// grid: (18, 128). blockIdx.x = query tile (64 queries), blockIdx.y = b*16+h.
// 256 threads. Per thread: S microtile 2 rows x 4 cols (key tile width 32),
// O accumulator 2 rows x 8 cols (head dim 64). Online softmax with 8-lane
// shuffle row reductions (lanes of one row group are contiguous within a warp).
__global__ void attn_kernel(const float* __restrict__ qkv,
                            const float* __restrict__ mask,
                            float* __restrict__ out) {
    const int z = blockIdx.y, b = z >> 4, h = z & 15;
    const int i0 = blockIdx.x * 64;

    __shared__ float Qt[64][65];        // [d][row]  16640 B
    __shared__ float KV[64 * 33];       // union: Kt [d][32 keys] (stride 33) / Vs [32 k][64 d] (stride 65)
    __shared__ float Ps[64 * 33];       // P tile [row][k], stride 33

    const int tid  = threadIdx.x;
    const int trow = tid >> 3;          // 0..31 -> rows trow*2, trow*2+1
    const int tcol = tid & 7;           // 0..7
    const int rb   = trow * 2;
    const int cb   = tcol * 4;          // S cols
    const int oc   = tcol * 8;          // O cols

    const float* qbase = qkv + (size_t)b * SEQ * H3 + (size_t)h * HDIM;
    const float* kbase = qbase + EMB;
    const float* vbase = qbase + 2 * EMB;

    // load Q tile (transposed, padded)
    #pragma unroll
    for (int it = 0; it < 16; ++it) {
        int idx = tid + it * 256;
        int r = idx >> 6, c = idx & 63;
        int gi = i0 + r;
        Qt[c][r] = (gi < SEQ) ? qbase[(size_t)gi * H3 + c] : 0.f;
    }

    const int gi[2] = { i0 + rb, i0 + rb + 1 };
    const bool isq[2] = { gi[0] >= NPATCH && gi[0] < SEQ, gi[1] >= NPATCH && gi[1] < SEQ };
    const float* mrowp[2];
    mrowp[0] = isq[0] ? mask + ((size_t)b * NQ + (size_t)(gi[0] - NPATCH)) * NPATCH : mask;
    mrowp[1] = isq[1] ? mask + ((size_t)b * NQ + (size_t)(gi[1] - NPATCH)) * NPATCH : mask;

    float mrun[2] = { -3.0e38f, -3.0e38f };
    float lrun[2] = { 0.f, 0.f };
    float acc[2][8];
    #pragma unroll
    for (int i = 0; i < 2; i++)
        #pragma unroll
        for (int j = 0; j < 8; j++) acc[i][j] = 0.f;

    for (int j0 = 0; j0 < SEQ; j0 += 32) {
        __syncthreads();   // prev-iter Vs reads done before Kt overwrite (also orders Q load, iter 0)
        // load K tile transposed: Kt[d][j] at KV[d*33 + j]
        #pragma unroll
        for (int it = 0; it < 8; ++it) {
            int idx = tid + it * 256;
            int j = idx >> 6, c = idx & 63;
            int gj = j0 + j;
            KV[c * 33 + j] = (gj < SEQ) ? kbase[(size_t)gj * H3 + c] : 0.f;
        }
        __syncthreads();

        // S = Q K^T for this thread's 2x4 microtile
        float s[2][4] = {{0.f,0.f,0.f,0.f},{0.f,0.f,0.f,0.f}};
        #pragma unroll
        for (int d = 0; d < 64; d++) {
            float a0 = Qt[d][rb], a1 = Qt[d][rb + 1];
            #pragma unroll
            for (int j = 0; j < 4; j++) {
                float kk = KV[d * 33 + cb + j];
                s[0][j] += a0 * kk;
                s[1][j] += a1 * kk;
            }
        }

        // scale + mask
        #pragma unroll
        for (int i = 0; i < 2; i++) {
            #pragma unroll
            for (int j = 0; j < 4; j++) {
                int gj = j0 + cb + j;
                float v = s[i][j] * ATTNSCALE;
                if (gj >= SEQ) v = -3.0e38f;
                else if (isq[i] && gj < NPATCH && mrowp[i][gj] <= 0.5f) v = NEG_INF_V;
                s[i][j] = v;
            }
        }

        // online softmax update (per row: reduce over 8 lanes of same trow)
        #pragma unroll
        for (int i = 0; i < 2; i++) {
            float mx = fmaxf(fmaxf(s[i][0], s[i][1]), fmaxf(s[i][2], s[i][3]));
            #pragma unroll
            for (int o = 1; o < 8; o <<= 1)
                mx = fmaxf(mx, __shfl_xor_sync(0xffffffffu, mx, o));
            float mnew = fmaxf(mrun[i], mx);
            float corr = expf(mrun[i] - mnew);
            mrun[i] = mnew;
            lrun[i] *= corr;
            #pragma unroll
            for (int j = 0; j < 8; j++) acc[i][j] *= corr;
            float sum = 0.f;
            #pragma unroll
            for (int j = 0; j < 4; j++) {
                float p = expf(s[i][j] - mnew);
                s[i][j] = p;
                sum += p;
            }
            #pragma unroll
            for (int o = 1; o < 8; o <<= 1)
                sum += __shfl_xor_sync(0xffffffffu, sum, o);
            lrun[i] += sum;
        }

        // write P tile
        #pragma unroll
        for (int i = 0; i < 2; i++)
            #pragma unroll
            for (int j = 0; j < 4; j++)
                Ps[(rb + i) * 33 + cb + j] = s[i][j];
        __syncthreads();   // Kt reads done + Ps visible

        // load V tile: Vs[k][c] at KV[k*65 + c]
        #pragma unroll
        for (int it = 0; it < 8; ++it) {
            int idx = tid + it * 256;
            int k = idx >> 6, c = idx & 63;
            int gk = j0 + k;
            KV[k * 65 + c] = (gk < SEQ) ? vbase[(size_t)gk * H3 + c] : 0.f;
        }
        __syncthreads();

        // O += P V
        #pragma unroll 8
        for (int k = 0; k < 32; k++) {
            float p0 = Ps[rb * 33 + k];
            float p1 = Ps[(rb + 1) * 33 + k];
            #pragma unroll
            for (int j = 0; j < 8; j++) {
                float vv = KV[k * 65 + oc + j];
                acc[0][j] += p0 * vv;
                acc[1][j] += p1 * vv;
            }
        }
    }

    // epilogue: normalize and store (heads merged into [tok, 1024])
    float* O = out + (size_t)b * SEQ * EMB + (size_t)h * HDIM;
    #pragma unroll
    for (int i = 0; i < 2; i++) {
        if (gi[i] < SEQ) {
            float inv = 1.0f / lrun[i];
            #pragma unroll
            for (int j = 0; j < 8; j++)
                O[(size_t)gi[i] * EMB + oc + j] = acc[i][j] * inv;
        }
    }
}

// ---------------- launch ----------------
extern "C" void kernel_launch(void* const* d_in, const int* in_sizes, int n_in,
                              void* d_out, int out_size) {
    (void)in_sizes; (void)n_in; (void)out_size;
    const float* x      = (const float*)d_in[0];
    const float* mask   = (const float*)d_in[1];
    const float* qkv_w  = (const float*)d_in[2];
    const float* proj_w = (const float*)d_in[3];
    const float* proj_b = (const float*)d_in[4];
    const float* ln1_g  = (const float*)d_in[5];
    const float* ln1_b  = (const float*)d_in[6];
    const float* ln2_g  = (const float*)d_in[7];
    const float* ln2_b  = (const float*)d_in[8];
    const float* fc1_w  = (const float*)d_in[9];
    const float* fc1_b  = (const float*)d_in[10];
    const float* fc2_w  = (const float*)d_in[11];
    const float* fc2_b  = (const float*)d_in[12];
    float* out = (float*)d_out;

    float *xn, *qkvb, *ao, *x1, *hb;
    cudaGetSymbolAddress((void**)&xn,   g_xn);
    cudaGetSymbolAddress((void**)&qkvb, g_qkv);
    cudaGetSymbolAddress((void**)&ao,   g_attnout);
    cudaGetSymbolAddress((void**)&x1,   g_x1);
    cudaGetSymbolAddress((void**)&hb,   g_h);

    const int MB = (NTOK + 127) / 128;  // 71

    // 1. LN1
    ln_kernel<<<NTOK, 256>>>(x, ln1_g, ln1_b, xn);
    // 2. QKV projection: [8992,1024] @ [1024,3072]
    gemm128<0><<<dim3(H3 / 128, MB), 256>>>(xn, EMB, qkv_w, H3, qkvb, H3,
                                            NTOK, H3, EMB, nullptr, nullptr, 0);
    // 3. fused attention (QK^T + mask + softmax + @V), heads merged to [tok,1024]
    attn_kernel<<<dim3(18, BATCH * NHEAD), 256>>>(qkvb, mask, ao);
    // 4. proj + bias + residual(x) -> x1
    gemm128<1><<<dim3(EMB / 128, MB), 256>>>(ao, EMB, proj_w, EMB, x1, EMB,
                                             NTOK, EMB, EMB, proj_b, x, EMB);
    // 5. LN2
    ln_kernel<<<NTOK, 256>>>(x1, ln2_g, ln2_b, xn);
    // 6. fc1 + bias + exact GELU
    gemm128<2><<<dim3(FHID / 128, MB), 256>>>(xn, EMB, fc1_w, FHID, hb, FHID,
                                              NTOK, FHID, EMB, fc1_b, nullptr, 0);
    // 7. fc2 + bias + residual(x1) -> out
    gemm128<1><<<dim3(EMB / 128, MB), 256>>>(hb, FHID, fc2_w, EMB, out, EMB,
                                             NTOK, EMB, FHID, fc2_b, x1, EMB);
}

// round 3
// speedup vs baseline: 1.0681x; 1.0681x over previous
#include <cuda_runtime.h>
#include <math.h>
#include <stdint.h>

// ---------------- problem constants ----------------
#define BATCH   8
#define SEQ     1124
#define EMB     1024
#define NHEAD   16
#define HDIM    64
#define NPATCH  1024
#define NQ      100
#define NTOK    (BATCH*SEQ)       // 8992
#define H3      3072
#define FHID    4096
#define ATTNSCALE 0.125f          // 64^-0.5
#define NEG_INF_V (-1000000000.0f)

// ---------------- scratch (static device memory; no allocs; ~367 MB) ----------------
__device__ float g_xn[(size_t)NTOK*EMB];
__device__ float g_qkv[(size_t)NTOK*H3];
__device__ float g_attnout[(size_t)NTOK*EMB];
__device__ float g_x1[(size_t)NTOK*EMB];
__device__ float g_h[(size_t)NTOK*FHID];

// ---------------- block reduction (sum, sumsq) ----------------
__device__ __forceinline__ void blockReduce2(float &a, float &b) {
    __shared__ float sa[8], sb[8];
    int lane = threadIdx.x & 31, w = threadIdx.x >> 5;
    #pragma unroll
    for (int o = 16; o; o >>= 1) {
        a += __shfl_xor_sync(0xffffffffu, a, o);
        b += __shfl_xor_sync(0xffffffffu, b, o);
    }
    if (lane == 0) { sa[w] = a; sb[w] = b; }
    __syncthreads();
    if (w == 0) {
        float ra = (lane < 8) ? sa[lane] : 0.f;
        float rb = (lane < 8) ? sb[lane] : 0.f;
        #pragma unroll
        for (int o = 4; o; o >>= 1) {
            ra += __shfl_xor_sync(0xffffffffu, ra, o);
            rb += __shfl_xor_sync(0xffffffffu, rb, o);
        }
        if (lane == 0) { sa[0] = ra; sb[0] = rb; }
    }
    __syncthreads();
    a = sa[0]; b = sb[0];
}

// ---------------- LayerNorm ----------------
__global__ void ln_kernel(const float* __restrict__ x, const float* __restrict__ g,
                          const float* __restrict__ be, float* __restrict__ out) {
    const int row = blockIdx.x, tid = threadIdx.x;
    const float* xr = x + (size_t)row * EMB;
    float v[4];
    float s = 0.f, sq = 0.f;
    #pragma unroll
    for (int i = 0; i < 4; i++) {
        float t = xr[tid + i * 256];
        v[i] = t; s += t; sq += t * t;
    }
    blockReduce2(s, sq);
    const float m   = s * (1.0f / EMB);
    const float var = sq * (1.0f / EMB) - m * m;
    const float inv = rsqrtf(var + 1e-6f);
    float* orow = out + (size_t)row * EMB;
    #pragma unroll
    for (int i = 0; i < 4; i++) {
        int c = tid + i * 256;
        orow[c] = (v[i] - m) * inv * g[c] + be[c];
    }
}

// ---------------- tensor-core TF32 helpers ----------------
__device__ __forceinline__ uint32_t f2tf32(float x) {
    uint32_t r;
    asm("cvt.rna.tf32.f32 %0, %1;" : "=r"(r) : "f"(x));
    return r;
}

__device__ __forceinline__ void mma_tf32(float* d, const uint32_t* a, const uint32_t* b) {
    asm volatile(
        "mma.sync.aligned.m16n8k8.row.col.f32.tf32.tf32.f32 "
        "{%0,%1,%2,%3}, {%4,%5,%6,%7}, {%8,%9}, {%0,%1,%2,%3};\n"
        : "+f"(d[0]), "+f"(d[1]), "+f"(d[2]), "+f"(d[3])
        : "r"(a[0]), "r"(a[1]), "r"(a[2]), "r"(a[3]), "r"(b[0]), "r"(b[1]));
}

// ---------------- TF32 tensor-core GEMM (3xTF32 compensated, ~fp32 accuracy) ------
// C[M,N] = A[M,K] @ B[K,N], all row-major. Requires N%128==0, K%16==0 (all call
// sites satisfy both). M guarded.
// Block tile 128x128xK16, 256 threads, warp grid 4(M)x2(N), warp tile 32x64.
// EPI: 0 = none; 1 = +bias +residual; 2 = +bias then exact GELU.
#define TCPAD 136   // row stride (words): bank = (8*t + g) -> conflict-free frags
template<int EPI>
__global__ void __launch_bounds__(256)
gemm_tc(const float* __restrict__ A, int lda,
        const float* __restrict__ B, int ldb,
        float* __restrict__ C, int ldc,
        int M, int N, int K,
        const float* __restrict__ bias,
        const float* __restrict__ resid, int ldr) {
    __shared__ float As[2][16][TCPAD];   // [hi/lo][k][m]
    __shared__ float Bs[2][16][TCPAD];   // [hi/lo][k][n]

    const int tid    = threadIdx.x;
    const int warp   = tid >> 5;
    const int lane   = tid & 31;
    const int g      = lane >> 2;     // 0..7
    const int t      = lane & 3;      // 0..3
    const int warp_m = warp & 3;      // 0..3 -> 32-row slabs
    const int warp_n = warp >> 2;     // 0..1 -> 64-col slabs
    const int row0   = blockIdx.y * 128;
    const int col0   = blockIdx.x * 128;

    float acc[2][8][4];
    #pragma unroll
    for (int mt = 0; mt < 2; mt++)
        #pragma unroll
        for (int nt = 0; nt < 8; nt++)
            #pragma unroll
            for (int i = 0; i < 4; i++) acc[mt][nt][i] = 0.f;

    // prefetch staging: per thread 2 float4 of A, 2 float4 of B
    float4 aR[2], bR[2];
    const int ar[2] = { (tid + 0)   >> 2, (tid + 256) >> 2 };   // 0..127
    const int ac4   = tid & 3;                                   // k group of 4
    const int br[2] = { (tid + 0)   >> 5, (tid + 256) >> 5 };   // 0..15
    const int bc4   = tid & 31;                                  // n group of 4

    // prologue prefetch k0 = 0
    {
        #pragma unroll
        for (int it = 0; it < 2; it++) {
            int gr = row0 + ar[it];
            aR[it] = (gr < M) ? *(const float4*)(A + (size_t)gr * lda + ac4 * 4)
                              : make_float4(0.f, 0.f, 0.f, 0.f);
            bR[it] = *(const float4*)(B + (size_t)(br[it]) * ldb + col0 + bc4 * 4);
        }
    }

    for (int k0 = 0; k0 < K; k0 += 16) {
        __syncthreads();   // prior compute done before SMEM overwrite
        // store prefetched tile with hi/lo tf32 split
        #pragma unroll
        for (int it = 0; it < 2; it++) {
            const float av[4] = { aR[it].x, aR[it].y, aR[it].z, aR[it].w };
            #pragma unroll
            for (int j = 0; j < 4; j++) {
                float x = av[j];
                uint32_t hb_ = f2tf32(x);
                float hf = __uint_as_float(hb_);
                As[0][ac4 * 4 + j][ar[it]] = hf;
                As[1][ac4 * 4 + j][ar[it]] = __uint_as_float(f2tf32(x - hf));
            }
            const float bv[4] = { bR[it].x, bR[it].y, bR[it].z, bR[it].w };
            #pragma unroll
            for (int j = 0; j < 4; j++) {
                float x = bv[j];
                uint32_t hb_ = f2tf32(x);
                float hf = __uint_as_float(hb_);
                Bs[0][br[it]][bc4 * 4 + j] = hf;
                Bs[1][br[it]][bc4 * 4 + j] = __uint_as_float(f2tf32(x - hf));
            }
        }
        __syncthreads();

        // prefetch next tile
        if (k0 + 16 < K) {
            int kn = k0 + 16;
            #pragma unroll
            for (int it = 0; it < 2; it++) {
                int gr = row0 + ar[it];
                aR[it] = (gr < M) ? *(const float4*)(A + (size_t)gr * lda + kn + ac4 * 4)
                                  : make_float4(0.f, 0.f, 0.f, 0.f);
                bR[it] = *(const float4*)(B + (size_t)(kn + br[it]) * ldb + col0 + bc4 * 4);
            }
        }

        // compute 2 x k8 steps
        #pragma unroll
        for (int ks = 0; ks < 16; ks += 8) {
            uint32_t ah[2][4], al[2][4];
            #pragma unroll
            for (int mt = 0; mt < 2; mt++) {
                int rb2 = warp_m * 32 + mt * 16;
                ah[mt][0] = __float_as_uint(As[0][ks + t    ][rb2 + g    ]);
                ah[mt][1] = __float_as_uint(As[0][ks + t    ][rb2 + g + 8]);
                ah[mt][2] = __float_as_uint(As[0][ks + t + 4][rb2 + g    ]);
                ah[mt][3] = __float_as_uint(As[0][ks + t + 4][rb2 + g + 8]);
                al[mt][0] = __float_as_uint(As[1][ks + t    ][rb2 + g    ]);
                al[mt][1] = __float_as_uint(As[1][ks + t    ][rb2 + g + 8]);
                al[mt][2] = __float_as_uint(As[1][ks + t + 4][rb2 + g    ]);
                al[mt][3] = __float_as_uint(As[1][ks + t + 4][rb2 + g + 8]);
            }
            #pragma unroll
            for (int nt = 0; nt < 8; nt++) {
                int cb2 = warp_n * 64 + nt * 8;
                uint32_t bh[2], bl[2];
                bh[0] = __float_as_uint(Bs[0][ks + t    ][cb2 + g]);
                bh[1] = __float_as_uint(Bs[0][ks + t + 4][cb2 + g]);
                bl[0] = __float_as_uint(Bs[1][ks + t    ][cb2 + g]);
                bl[1] = __float_as_uint(Bs[1][ks + t + 4][cb2 + g]);
                #pragma unroll
                for (int mt = 0; mt < 2; mt++) {
                    mma_tf32(acc[mt][nt], ah[mt], bh);   // hi*hi
                    mma_tf32(acc[mt][nt], ah[mt], bl);   // hi*lo
                    mma_tf32(acc[mt][nt], al[mt], bh);   // lo*hi
                }
            }
        }
    }

    // epilogue
    #pragma unroll
    for (int mt = 0; mt < 2; mt++) {
        #pragma unroll
        for (int nt = 0; nt < 8; nt++) {
            #pragma unroll
            for (int i = 0; i < 4; i++) {
                int gr = row0 + warp_m * 32 + mt * 16 + g + ((i >> 1) ? 8 : 0);
                int gc = col0 + warp_n * 64 + nt * 8 + 2 * t + (i & 1);
                if (gr >= M) continue;
                float v = acc[mt][nt][i];
                if (EPI >= 1) v += bias[gc];
                if (EPI == 1) v += resid[(size_t)gr * ldr + gc];
                if (EPI == 2) v = 0.5f * v * (1.0f + erff(v * 0.70710678118654752f));
                C[(size_t)gr * ldc + gc] = v;
            }
        }
    }
}

// ---------------- fused flash-style attention (unchanged from R2) ----------------
__global__ void attn_kernel(const float* __restrict__ qkv,
                            const float* __restrict__ mask,
                            float* __restrict__ out) {
    const int z = blockIdx.y, b = z >> 4, h = z & 15;
    const int i0 = blockIdx.x * 64;

    __shared__ float Qt[64][65];
    __shared__ float KV[64 * 33];       // union: Kt [d][32] (stride 33) / Vs [32][64] (stride 65)
    __shared__ float Ps[64 * 33];

    const int tid  = threadIdx.x;
    const int trow = tid >> 3;
    const int tcol = tid & 7;
    const int rb   = trow * 2;
    const int cb   = tcol * 4;
    const int oc   = tcol * 8;

    const float* qbase = qkv + (size_t)b * SEQ * H3 + (size_t)h * HDIM;
    const float* kbase = qbase + EMB;
    const float* vbase = qbase + 2 * EMB;

    #pragma unroll
    for (int it = 0; it < 16; ++it) {
        int idx = tid + it * 256;
        int r = idx >> 6, c = idx & 63;
        int gi = i0 + r;
        Qt[c][r] = (gi < SEQ) ? qbase[(size_t)gi * H3 + c] : 0.f;
    }

    const int gi[2] = { i0 + rb, i0 + rb + 1 };
    const bool isq[2] = { gi[0] >= NPATCH && gi[0] < SEQ, gi[1] >= NPATCH && gi[1] < SEQ };
    const float* mrowp[2];
    mrowp[0] = isq[0] ? mask + ((size_t)b * NQ + (size_t)(gi[0] - NPATCH)) * NPATCH : mask;
    mrowp[1] = isq[1] ? mask + ((size_t)b * NQ + (size_t)(gi[1] - NPATCH)) * NPATCH : mask;

    float mrun[2] = { -3.0e38f, -3.0e38f };
    float lrun[2] = { 0.f, 0.f };
    float acc[2][8];
    #pragma unroll
    for (int i = 0; i < 2; i++)
        #pragma unroll
        for (int j = 0; j < 8; j++) acc[i][j] = 0.f;

    for (int j0 = 0; j0 < SEQ; j0 += 32) {
        __syncthreads();
        #pragma unroll
        for (int it = 0; it < 8; ++it) {
            int idx = tid + it * 256;
            int j = idx >> 6, c = idx & 63;
            int gj = j0 + j;
            KV[c * 33 + j] = (gj < SEQ) ? kbase[(size_t)gj * H3 + c] : 0.f;
        }
        __syncthreads();

        float s[2][4] = {{0.f,0.f,0.f,0.f},{0.f,0.f,0.f,0.f}};
        #pragma unroll
        for (int d = 0; d < 64; d++) {
            float a0 = Qt[d][rb], a1 = Qt[d][rb + 1];
            #pragma unroll
            for (int j = 0; j < 4; j++) {
                float kk = KV[d * 33 + cb + j];
                s[0][j] += a0 * kk;
                s[1][j] += a1 * kk;
            }
        }

        #pragma unroll
        for (int i = 0; i < 2; i++) {
            #pragma unroll
            for (int j = 0; j < 4; j++) {
                int gj = j0 + cb + j;
                float v = s[i][j] * ATTNSCALE;
                if (gj >= SEQ) v = -3.0e38f;
                else if (isq[i] && gj < NPATCH && mrowp[i][gj] <= 0.5f) v = NEG_INF_V;
                s[i][j] = v;
            }
        }

        #pragma unroll
        for (int i = 0; i < 2; i++) {
            float mx = fmaxf(fmaxf(s[i][0], s[i][1]), fmaxf(s[i][2], s[i][3]));
            #pragma unroll
            for (int o = 1; o < 8; o <<= 1)
                mx = fmaxf(mx, __shfl_xor_sync(0xffffffffu, mx, o));
            float mnew = fmaxf(mrun[i], mx);
            float corr = expf(mrun[i] - mnew);
            mrun[i] = mnew;
            lrun[i] *= corr;
            #pragma unroll
            for (int j = 0; j < 8; j++) acc[i][j] *= corr;
            float sum = 0.f;
            #pragma unroll
            for (int j = 0; j < 4; j++) {
                float p = expf(s[i][j] - mnew);
                s[i][j] = p;
                sum += p;
            }
            #pragma unroll
            for (int o = 1; o < 8; o <<= 1)
                sum += __shfl_xor_sync(0xffffffffu, sum, o);
            lrun[i] += sum;
        }

        #pragma unroll
        for (int i = 0; i < 2; i++)
            #pragma unroll
            for (int j = 0; j < 4; j++)
                Ps[(rb + i) * 33 + cb + j] = s[i][j];
        __syncthreads();

        #pragma unroll
        for (int it = 0; it < 8; ++it) {
            int idx = tid + it * 256;
            int k = idx >> 6, c = idx & 63;
            int gk = j0 + k;
            KV[k * 65 + c] = (gk < SEQ) ? vbase[(size_t)gk * H3 + c] : 0.f;
        }
        __syncthreads();

        #pragma unroll 8
        for (int k = 0; k < 32; k++) {
            float p0 = Ps[rb * 33 + k];
            float p1 = Ps[(rb + 1) * 33 + k];
            #pragma unroll
            for (int j = 0; j < 8; j++) {
                float vv = KV[k * 65 + oc + j];
                acc[0][j] += p0 * vv;
                acc[1][j] += p1 * vv;
            }
        }
    }

    float* O = out + (size_t)b * SEQ * EMB + (size_t)h * HDIM;
    #pragma unroll
    for (int i = 0; i < 2; i++) {
        if (gi[i] < SEQ) {
            float inv = 1.0f / lrun[i];
            #pragma unroll
            for (int j = 0; j < 8; j++)
                O[(size_t)gi[i] * EMB + oc + j] = acc[i][j] * inv;
        }
    }
}

// ---------------- launch ----------------
extern "C" void kernel_launch(void* const* d_in, const int* in_sizes, int n_in,
                              void* d_out, int out_size) {
    (void)in_sizes; (void)n_in; (void)out_size;
    const float* x      = (const float*)d_in[0];
    const float* mask   = (const float*)d_in[1];
    const float* qkv_w  = (const float*)d_in[2];
    const float* proj_w = (const float*)d_in[3];
    const float* proj_b = (const float*)d_in[4];
    const float* ln1_g  = (const float*)d_in[5];
    const float* ln1_b  = (const float*)d_in[6];
    const float* ln2_g  = (const float*)d_in[7];
    const float* ln2_b  = (const float*)d_in[8];
    const float* fc1_w  = (const float*)d_in[9];
    const float* fc1_b  = (const float*)d_in[10];
    const float* fc2_w  = (const float*)d_in[11];
    const float* fc2_b  = (const float*)d_in[12];
    float* out = (float*)d_out;

    float *xn, *qkvb, *ao, *x1, *hb;
    cudaGetSymbolAddress((void**)&xn,   g_xn);
    cudaGetSymbolAddress((void**)&qkvb, g_qkv);
    cudaGetSymbolAddress((void**)&ao,   g_attnout);
    cudaGetSymbolAddress((void**)&x1,   g_x1);
    cudaGetSymbolAddress((void**)&hb,   g_h);

    const int MB = (NTOK + 127) / 128;  // 71

    // 1. LN1
    ln_kernel<<<NTOK, 256>>>(x, ln1_g, ln1_b, xn);
    // 2. QKV projection
    gemm_tc<0><<<dim3(H3 / 128, MB), 256>>>(xn, EMB, qkv_w, H3, qkvb, H3,
                                            NTOK, H3, EMB, nullptr, nullptr, 0);
    // 3. fused attention
    attn_kernel<<<dim3(18, BATCH * NHEAD), 256>>>(qkvb, mask, ao);
    // 4. proj + bias + residual(x) -> x1
    gemm_tc<1><<<dim3(EMB / 128, MB), 256>>>(ao, EMB, proj_w, EMB, x1, EMB,
                                             NTOK, EMB, EMB, proj_b, x, EMB);
    // 5. LN2
    ln_kernel<<<NTOK, 256>>>(x1, ln2_g, ln2_b, xn);
    // 6. fc1 + bias + exact GELU
    gemm_tc<2><<<dim3(FHID / 128, MB), 256>>>(xn, EMB, fc1_w, FHID, hb, FHID,
                                              NTOK, FHID, EMB, fc1_b, nullptr, 0);
    // 7. fc2 + bias + residual(x1) -> out
    gemm_tc<1><<<dim3(EMB / 128, MB), 256>>>(hb, FHID, fc2_w, EMB, out, EMB,
                                             NTOK, EMB, FHID, fc2_b, x1, EMB);
}

// round 5
// speedup vs baseline: 1.7691x; 1.6564x over previous
#include <cuda_runtime.h>
#include <cuda_bf16.h>
#include <math.h>
#include <stdint.h>

// ---------------- problem constants ----------------
#define BATCH   8
#define SEQ     1124
#define EMB     1024
#define NHEAD   16
#define HDIM    64
#define NPATCH  1024
#define NQ      100
#define NTOK    (BATCH*SEQ)       // 8992
#define H3      3072
#define FHID    4096
#define ATTNSCALE 0.125f
#define NEG_INF_V (-1000000000.0f)

typedef __nv_bfloat16 bf16;

// ---------------- scratch (static device memory; no allocs) ----------------
__device__ __align__(256) bf16  g_xn_hi[(size_t)NTOK*EMB];
__device__ __align__(256) bf16  g_xn_lo[(size_t)NTOK*EMB];
__device__ __align__(256) float g_qkv[(size_t)NTOK*H3];
__device__ __align__(256) bf16  g_ao_hi[(size_t)NTOK*EMB];
__device__ __align__(256) bf16  g_ao_lo[(size_t)NTOK*EMB];
__device__ __align__(256) float g_x1[(size_t)NTOK*EMB];
__device__ __align__(256) bf16  g_hb_hi[(size_t)NTOK*FHID];
__device__ __align__(256) bf16  g_hb_lo[(size_t)NTOK*FHID];
// transposed + split weights: [N, K]
__device__ __align__(256) bf16  g_wqkv_hi[(size_t)H3*EMB];
__device__ __align__(256) bf16  g_wqkv_lo[(size_t)H3*EMB];
__device__ __align__(256) bf16  g_wproj_hi[(size_t)EMB*EMB];
__device__ __align__(256) bf16  g_wproj_lo[(size_t)EMB*EMB];
__device__ __align__(256) bf16  g_wfc1_hi[(size_t)FHID*EMB];
__device__ __align__(256) bf16  g_wfc1_lo[(size_t)FHID*EMB];
__device__ __align__(256) bf16  g_wfc2_hi[(size_t)EMB*FHID];
__device__ __align__(256) bf16  g_wfc2_lo[(size_t)EMB*FHID];

// ---------------- helpers ----------------
__device__ __forceinline__ uint32_t smem_u32(const void* p) {
    uint32_t a;
    asm("{ .reg .u64 t; cvta.to.shared.u64 t, %1; cvt.u32.u64 %0, t; }" : "=r"(a) : "l"(p));
    return a;
}

__device__ __forceinline__ void cp16(uint32_t dst, const void* src, int bytes) {
    asm volatile("cp.async.cg.shared.global [%0], [%1], 16, %2;"
                 :: "r"(dst), "l"(src), "r"(bytes) : "memory");
}
#define CP_COMMIT() asm volatile("cp.async.commit_group;" ::: "memory")
#define CP_WAIT1()  asm volatile("cp.async.wait_group 1;" ::: "memory")

__device__ __forceinline__ void mma_bf16(float* d, const uint32_t* a, const uint32_t* b) {
    asm volatile(
        "mma.sync.aligned.m16n8k16.row.col.f32.bf16.bf16.f32 "
        "{%0,%1,%2,%3}, {%4,%5,%6,%7}, {%8,%9}, {%0,%1,%2,%3};\n"
        : "+f"(d[0]), "+f"(d[1]), "+f"(d[2]), "+f"(d[3])
        : "r"(a[0]), "r"(a[1]), "r"(a[2]), "r"(a[3]), "r"(b[0]), "r"(b[1]));
}

__device__ __forceinline__ void split_bf16(float x, bf16& h, bf16& l) {
    h = __float2bfloat16_rn(x);
    l = __float2bfloat16_rn(x - __bfloat162float(h));
}

// ---------------- block reduction (sum, sumsq) ----------------
__device__ __forceinline__ void blockReduce2(float &a, float &b) {
    __shared__ float sa[8], sb[8];
    int lane = threadIdx.x & 31, w = threadIdx.x >> 5;
    #pragma unroll
    for (int o = 16; o; o >>= 1) {
        a += __shfl_xor_sync(0xffffffffu, a, o);
        b += __shfl_xor_sync(0xffffffffu, b, o);
    }
    if (lane == 0) { sa[w] = a; sb[w] = b; }
    __syncthreads();
    if (w == 0) {
        float ra = (lane < 8) ? sa[lane] : 0.f;
        float rb = (lane < 8) ? sb[lane] : 0.f;
        #pragma unroll
        for (int o = 4; o; o >>= 1) {
            ra += __shfl_xor_sync(0xffffffffu, ra, o);
            rb += __shfl_xor_sync(0xffffffffu, rb, o);
        }
        if (lane == 0) { sa[0] = ra; sb[0] = rb; }
    }
    __syncthreads();
    a = sa[0]; b = sb[0];
}

// ---------------- LayerNorm -> hi/lo bf16 ----------------
__global__ void ln_kernel(const float* __restrict__ x, const float* __restrict__ g,
                          const float* __restrict__ be,
                          bf16* __restrict__ ohi, bf16* __restrict__ olo) {
    const int row = blockIdx.x, tid = threadIdx.x;
    const float* xr = x + (size_t)row * EMB;
    float v[4];
    float s = 0.f, sq = 0.f;
    #pragma unroll
    for (int i = 0; i < 4; i++) {
        float t = xr[tid + i * 256];
        v[i] = t; s += t; sq += t * t;
    }
    blockReduce2(s, sq);
    const float m   = s * (1.0f / EMB);
    const float var = sq * (1.0f / EMB) - m * m;
    const float inv = rsqrtf(var + 1e-6f);
    #pragma unroll
    for (int i = 0; i < 4; i++) {
        int c = tid + i * 256;
        float o = (v[i] - m) * inv * g[c] + be[c];
        bf16 h, l; split_bf16(o, h, l);
        ohi[(size_t)row * EMB + c] = h;
        olo[(size_t)row * EMB + c] = l;
    }
}

// ---------------- weight transpose + split: W[K,N] f32 -> T[N,K] hi/lo bf16 -------
__global__ void wconv_kernel(const float* __restrict__ W, int K, int N,
                             bf16* __restrict__ Thi, bf16* __restrict__ Tlo) {
    __shared__ float t[32][33];
    const int k0 = blockIdx.y * 32, n0 = blockIdx.x * 32;
    const int tx = threadIdx.x, ty = threadIdx.y;
    #pragma unroll
    for (int i = 0; i < 4; i++)
        t[ty + i * 8][tx] = W[(size_t)(k0 + ty + i * 8) * N + n0 + tx];
    __syncthreads();
    #pragma unroll
    for (int i = 0; i < 4; i++) {
        int n = ty + i * 8;
        float x = t[tx][n];
        bf16 h, l; split_bf16(x, h, l);
        Thi[(size_t)(n0 + n) * K + k0 + tx] = h;
        Tlo[(size_t)(n0 + n) * K + k0 + tx] = l;
    }
}

// ---------------- bf16 mma.sync GEMM, hi/lo compensated ----------------
// C[M,N] = A[M,K] @ B^T, A [M,K] hi/lo bf16, B stored [N,K] hi/lo bf16.
// Block tile 128x128, K-chunk 32 (2 x k16 mma steps), 256 thr, warp grid 4x2,
// warp tile 32x64. cp.async double-buffered SMEM.
// SMEM word layout per matrix: [row][kk] packed bf16x2, row stride 20 words
// (16 used + 4 pad -> (g*20+t)%32 all-distinct banks for fragment loads).
// EPI: 0 = f32 C; 1 = +bias +resid f32 C; 2 = +bias +GELU -> hi/lo bf16.
#define ST_A_HI  0
#define ST_A_LO  10240
#define ST_B_HI  20480
#define ST_B_LO  30720
#define ST_STAGE 40960
#define GEMM_SMEM_BYTES (2 * ST_STAGE)   // 81920

template<int EPI>
__global__ void __launch_bounds__(256, 2)
gemm_mma(const bf16* __restrict__ Ah, const bf16* __restrict__ Al, int lda,
         const bf16* __restrict__ Bh, const bf16* __restrict__ Bl, int K,
         float* __restrict__ C, int ldc, int M,
         const float* __restrict__ bias,
         const float* __restrict__ resid, int ldr,
         bf16* __restrict__ Ohi, bf16* __restrict__ Olo) {
    extern __shared__ char smem[];
    const uint32_t sbase = smem_u32(smem);

    const int tid    = threadIdx.x;
    const int warp   = tid >> 5;
    const int lane   = tid & 31;
    const int g      = lane >> 2;
    const int t      = lane & 3;
    const int warp_m = warp & 3;
    const int warp_n = warp >> 2;
    const int row0   = blockIdx.y * 128;
    const int col0   = blockIdx.x * 128;

    // per-thread cp.async slots: 2 iters, each 16B into 4 matrices
    const int m_   = tid >> 2;          // 0..63 (+64 on iter 1)
    const int q_   = tid & 3;           // 16B quad within 32-k row

    float acc[2][8][4];
    #pragma unroll
    for (int mt = 0; mt < 2; mt++)
        #pragma unroll
        for (int nt = 0; nt < 8; nt++)
            #pragma unroll
            for (int i = 0; i < 4; i++) acc[mt][nt][i] = 0.f;

    const int nch = K >> 5;

    // ---- issue chunk c into stage s ----
    auto issue = [&](int c, int s) {
        const int k0 = c << 5;
        const uint32_t sb = sbase + s * ST_STAGE;
        #pragma unroll
        for (int i = 0; i < 2; i++) {
            const int m = m_ + i * 64;
            const uint32_t d = sb + m * 80 + q_ * 16;
            const int gr = row0 + m;
            const int ok = (gr < M) ? 16 : 0;
            const size_t aoff = (size_t)(ok ? gr : 0) * lda + k0 + q_ * 8;
            cp16(d + ST_A_HI, Ah + aoff, ok);
            cp16(d + ST_A_LO, Al + aoff, ok);
            const size_t boff = (size_t)(col0 + m) * K + k0 + q_ * 8;
            cp16(d + ST_B_HI, Bh + boff, 16);
            cp16(d + ST_B_LO, Bl + boff, 16);
        }
    };

    issue(0, 0);
    CP_COMMIT();

    for (int c = 0; c < nch; ++c) {
        const int s = c & 1;
        if (c + 1 < nch) issue(c + 1, s ^ 1);
        CP_COMMIT();
        CP_WAIT1();
        __syncthreads();

        const uint32_t* sAh = (const uint32_t*)(smem + s * ST_STAGE + ST_A_HI);
        const uint32_t* sAl = (const uint32_t*)(smem + s * ST_STAGE + ST_A_LO);
        const uint32_t* sBh = (const uint32_t*)(smem + s * ST_STAGE + ST_B_HI);
        const uint32_t* sBl = (const uint32_t*)(smem + s * ST_STAGE + ST_B_LO);

        #pragma unroll
        for (int ks = 0; ks < 2; ++ks) {
            const int kw = ks * 8;
            uint32_t ah[2][4], al[2][4];
            #pragma unroll
            for (int mt = 0; mt < 2; mt++) {
                const int r = warp_m * 32 + mt * 16 + g;
                ah[mt][0] = sAh[r       * 20 + kw + t];
                ah[mt][1] = sAh[(r + 8) * 20 + kw + t];
                ah[mt][2] = sAh[r       * 20 + kw + t + 4];
                ah[mt][3] = sAh[(r + 8) * 20 + kw + t + 4];
                al[mt][0] = sAl[r       * 20 + kw + t];
                al[mt][1] = sAl[(r + 8) * 20 + kw + t];
                al[mt][2] = sAl[r       * 20 + kw + t + 4];
                al[mt][3] = sAl[(r + 8) * 20 + kw + t + 4];
            }
            #pragma unroll
            for (int nt = 0; nt < 8; nt++) {
                const int n = warp_n * 64 + nt * 8 + g;
                uint32_t bh[2], bl[2];
                bh[0] = sBh[n * 20 + kw + t];
                bh[1] = sBh[n * 20 + kw + t + 4];
                bl[0] = sBl[n * 20 + kw + t];
                bl[1] = sBl[n * 20 + kw + t + 4];
                #pragma unroll
                for (int mt = 0; mt < 2; mt++) {
                    mma_bf16(acc[mt][nt], ah[mt], bh);   // hi*hi
                    mma_bf16(acc[mt][nt], al[mt], bh);   // lo*hi
                    mma_bf16(acc[mt][nt], ah[mt], bl);   // hi*lo
                }
            }
        }
        __syncthreads();
    }

    // epilogue: c0={g,2t} c1={g,2t+1} c2={g+8,2t} c3={g+8,2t+1}
    #pragma unroll
    for (int mt = 0; mt < 2; mt++) {
        #pragma unroll
        for (int nt = 0; nt < 8; nt++) {
            #pragma unroll
            for (int i = 0; i < 4; i++) {
                const int gr = row0 + warp_m * 32 + mt * 16 + g + ((i >> 1) ? 8 : 0);
                const int gc = col0 + warp_n * 64 + nt * 8 + 2 * t + (i & 1);
                if (gr >= M) continue;
                float v = acc[mt][nt][i];
                if (EPI >= 1) v += bias[gc];
                if (EPI == 1) {
                    v += resid[(size_t)gr * ldr + gc];
                    C[(size_t)gr * ldc + gc] = v;
                } else if (EPI == 2) {
                    v = 0.5f * v * (1.0f + erff(v * 0.70710678118654752f));
                    bf16 h, l; split_bf16(v, h, l);
                    Ohi[(size_t)gr * ldc + gc] = h;
                    Olo[(size_t)gr * ldc + gc] = l;
                } else {
                    C[(size_t)gr * ldc + gc] = v;
                }
            }
        }
    }
}

// ---------------- fused flash-style attention (epilogue -> hi/lo) ----------------
__global__ void attn_kernel(const float* __restrict__ qkv,
                            const float* __restrict__ mask,
                            bf16* __restrict__ ohi, bf16* __restrict__ olo) {
    const int z = blockIdx.y, b = z >> 4, h = z & 15;
    const int i0 = blockIdx.x * 64;

    __shared__ float Qt[64][65];
    __shared__ float KV[64 * 33];
    __shared__ float Ps[64 * 33];

    const int tid  = threadIdx.x;
    const int trow = tid >> 3;
    const int tcol = tid & 7;
    const int rb   = trow * 2;
    const int cb   = tcol * 4;
    const int oc   = tcol * 8;

    const float* qbase = qkv + (size_t)b * SEQ * H3 + (size_t)h * HDIM;
    const float* kbase = qbase + EMB;
    const float* vbase = qbase + 2 * EMB;

    #pragma unroll
    for (int it = 0; it < 16; ++it) {
        int idx = tid + it * 256;
        int r = idx >> 6, c = idx & 63;
        int gi = i0 + r;
        Qt[c][r] = (gi < SEQ) ? qbase[(size_t)gi * H3 + c] : 0.f;
    }

    const int gi[2] = { i0 + rb, i0 + rb + 1 };
    const bool isq[2] = { gi[0] >= NPATCH && gi[0] < SEQ, gi[1] >= NPATCH && gi[1] < SEQ };
    const float* mrowp[2];
    mrowp[0] = isq[0] ? mask + ((size_t)b * NQ + (size_t)(gi[0] - NPATCH)) * NPATCH : mask;
    mrowp[1] = isq[1] ? mask + ((size_t)b * NQ + (size_t)(gi[1] - NPATCH)) * NPATCH : mask;

    float mrun[2] = { -3.0e38f, -3.0e38f };
    float lrun[2] = { 0.f, 0.f };
    float acc[2][8];
    #pragma unroll
    for (int i = 0; i < 2; i++)
        #pragma unroll
        for (int j = 0; j < 8; j++) acc[i][j] = 0.f;

    for (int j0 = 0; j0 < SEQ; j0 += 32) {
        __syncthreads();
        #pragma unroll
        for (int it = 0; it < 8; ++it) {
            int idx = tid + it * 256;
            int j = idx >> 6, c = idx & 63;
            int gj = j0 + j;
            KV[c * 33 + j] = (gj < SEQ) ? kbase[(size_t)gj * H3 + c] : 0.f;
        }
        __syncthreads();

        float s[2][4] = {{0.f,0.f,0.f,0.f},{0.f,0.f,0.f,0.f}};
        #pragma unroll
        for (int d = 0; d < 64; d++) {
            float a0 = Qt[d][rb], a1 = Qt[d][rb + 1];
            #pragma unroll
            for (int j = 0; j < 4; j++) {
                float kk = KV[d * 33 + cb + j];
                s[0][j] += a0 * kk;
                s[1][j] += a1 * kk;
            }
        }

        #pragma unroll
        for (int i = 0; i < 2; i++) {
            #pragma unroll
            for (int j = 0; j < 4; j++) {
                int gj = j0 + cb + j;
                float v = s[i][j] * ATTNSCALE;
                if (gj >= SEQ) v = -3.0e38f;
                else if (isq[i] && gj < NPATCH && mrowp[i][gj] <= 0.5f) v = NEG_INF_V;
                s[i][j] = v;
            }
        }

        #pragma unroll
        for (int i = 0; i < 2; i++) {
            float mx = fmaxf(fmaxf(s[i][0], s[i][1]), fmaxf(s[i][2], s[i][3]));
            #pragma unroll
            for (int o = 1; o < 8; o <<= 1)
                mx = fmaxf(mx, __shfl_xor_sync(0xffffffffu, mx, o));
            float mnew = fmaxf(mrun[i], mx);
            float corr = expf(mrun[i] - mnew);
            mrun[i] = mnew;
            lrun[i] *= corr;
            #pragma unroll
            for (int j = 0; j < 8; j++) acc[i][j] *= corr;
            float sum = 0.f;
            #pragma unroll
            for (int j = 0; j < 4; j++) {
                float p = expf(s[i][j] - mnew);
                s[i][j] = p;
                sum += p;
            }
            #pragma unroll
            for (int o = 1; o < 8; o <<= 1)
                sum += __shfl_xor_sync(0xffffffffu, sum, o);
            lrun[i] += sum;
        }

        #pragma unroll
        for (int i = 0; i < 2; i++)
            #pragma unroll
            for (int j = 0; j < 4; j++)
                Ps[(rb + i) * 33 + cb + j] = s[i][j];
        __syncthreads();

        #pragma unroll
        for (int it = 0; it < 8; ++it) {
            int idx = tid + it * 256;
            int k = idx >> 6, c = idx & 63;
            int gk = j0 + k;
            KV[k * 65 + c] = (gk < SEQ) ? vbase[(size_t)gk * H3 + c] : 0.f;
        }
        __syncthreads();

        #pragma unroll 8
        for (int k = 0; k < 32; k++) {
            float p0 = Ps[rb * 33 + k];
            float p1 = Ps[(rb + 1) * 33 + k];
            #pragma unroll
            for (int j = 0; j < 8; j++) {
                float vv = KV[k * 65 + oc + j];
                acc[0][j] += p0 * vv;
                acc[1][j] += p1 * vv;
            }
        }
    }

    #pragma unroll
    for (int i = 0; i < 2; i++) {
        if (gi[i] < SEQ) {
            float inv = 1.0f / lrun[i];
            size_t base = (size_t)b * SEQ * EMB + (size_t)gi[i] * EMB + (size_t)h * HDIM;
            #pragma unroll
            for (int j = 0; j < 8; j++) {
                float v = acc[i][j] * inv;
                bf16 hh, ll; split_bf16(v, hh, ll);
                ohi[base + oc + j] = hh;
                olo[base + oc + j] = ll;
            }
        }
    }
}

// ---------------- launch ----------------
extern "C" void kernel_launch(void* const* d_in, const int* in_sizes, int n_in,
                              void* d_out, int out_size) {
    (void)in_sizes; (void)n_in; (void)out_size;
    const float* x      = (const float*)d_in[0];
    const float* mask   = (const float*)d_in[1];
    const float* qkv_w  = (const float*)d_in[2];
    const float* proj_w = (const float*)d_in[3];
    const float* proj_b = (const float*)d_in[4];
    const float* ln1_g  = (const float*)d_in[5];
    const float* ln1_b  = (const float*)d_in[6];
    const float* ln2_g  = (const float*)d_in[7];
    const float* ln2_b  = (const float*)d_in[8];
    const float* fc1_w  = (const float*)d_in[9];
    const float* fc1_b  = (const float*)d_in[10];
    const float* fc2_w  = (const float*)d_in[11];
    const float* fc2_b  = (const float*)d_in[12];
    float* out = (float*)d_out;

    bf16 *xnh, *xnl, *aoh, *aol, *hbh, *hbl;
    bf16 *wqh, *wql, *wph, *wpl, *w1h, *w1l, *w2h, *w2l;
    float *qkvb, *x1;
    cudaGetSymbolAddress((void**)&xnh, g_xn_hi);  cudaGetSymbolAddress((void**)&xnl, g_xn_lo);
    cudaGetSymbolAddress((void**)&aoh, g_ao_hi);  cudaGetSymbolAddress((void**)&aol, g_ao_lo);
    cudaGetSymbolAddress((void**)&hbh, g_hb_hi);  cudaGetSymbolAddress((void**)&hbl, g_hb_lo);
    cudaGetSymbolAddress((void**)&wqh, g_wqkv_hi); cudaGetSymbolAddress((void**)&wql, g_wqkv_lo);
    cudaGetSymbolAddress((void**)&wph, g_wproj_hi); cudaGetSymbolAddress((void**)&wpl, g_wproj_lo);
    cudaGetSymbolAddress((void**)&w1h, g_wfc1_hi); cudaGetSymbolAddress((void**)&w1l, g_wfc1_lo);
    cudaGetSymbolAddress((void**)&w2h, g_wfc2_hi); cudaGetSymbolAddress((void**)&w2l, g_wfc2_lo);
    cudaGetSymbolAddress((void**)&qkvb, g_qkv);
    cudaGetSymbolAddress((void**)&x1, g_x1);

    cudaFuncSetAttribute(gemm_mma<0>, cudaFuncAttributeMaxDynamicSharedMemorySize, GEMM_SMEM_BYTES);
    cudaFuncSetAttribute(gemm_mma<1>, cudaFuncAttributeMaxDynamicSharedMemorySize, GEMM_SMEM_BYTES);
    cudaFuncSetAttribute(gemm_mma<2>, cudaFuncAttributeMaxDynamicSharedMemorySize, GEMM_SMEM_BYTES);

    const dim3 wblk(32, 8);
    const int MB = (NTOK + 127) / 128;  // 71

    // weight transpose + split
    wconv_kernel<<<dim3(H3/32,  EMB/32),  wblk>>>(qkv_w,  EMB,  H3,   wqh, wql);
    wconv_kernel<<<dim3(EMB/32, EMB/32),  wblk>>>(proj_w, EMB,  EMB,  wph, wpl);
    wconv_kernel<<<dim3(FHID/32,EMB/32),  wblk>>>(fc1_w,  EMB,  FHID, w1h, w1l);
    wconv_kernel<<<dim3(EMB/32, FHID/32), wblk>>>(fc2_w,  FHID, EMB,  w2h, w2l);

    // 1. LN1 -> hi/lo
    ln_kernel<<<NTOK, 256>>>(x, ln1_g, ln1_b, xnh, xnl);
    // 2. QKV = xn @ qkv_w -> f32
    gemm_mma<0><<<dim3(H3/128, MB), 256, GEMM_SMEM_BYTES>>>(
        xnh, xnl, EMB, wqh, wql, EMB, qkvb, H3, NTOK, nullptr, nullptr, 0, nullptr, nullptr);
    // 3. fused attention -> hi/lo
    attn_kernel<<<dim3(18, BATCH * NHEAD), 256>>>(qkvb, mask, aoh, aol);
    // 4. x1 = ao @ proj_w + b + x
    gemm_mma<1><<<dim3(EMB/128, MB), 256, GEMM_SMEM_BYTES>>>(
        aoh, aol, EMB, wph, wpl, EMB, x1, EMB, NTOK, proj_b, x, EMB, nullptr, nullptr);
    // 5. LN2 -> hi/lo
    ln_kernel<<<NTOK, 256>>>(x1, ln2_g, ln2_b, xnh, xnl);
    // 6. hb = gelu(xn @ fc1_w + b) -> hi/lo
    gemm_mma<2><<<dim3(FHID/128, MB), 256, GEMM_SMEM_BYTES>>>(
        xnh, xnl, EMB, w1h, w1l, EMB, nullptr, FHID, NTOK, fc1_b, nullptr, 0, hbh, hbl);
    // 7. out = hb @ fc2_w + b + x1
    gemm_mma<1><<<dim3(EMB/128, MB), 256, GEMM_SMEM_BYTES>>>(
        hbh, hbl, FHID, w2h, w2l, FHID, out, EMB, NTOK, fc2_b, x1, EMB, nullptr, nullptr);
}

// round 8
// speedup vs baseline: 2.0006x; 1.1309x over previous
#include <cuda_runtime.h>
#include <cuda_fp16.h>
#include <math.h>
#include <stdint.h>

// ---------------- problem constants ----------------
#define BATCH   8
#define SEQ     1124
#define EMB     1024
#define NHEAD   16
#define HDIM    64
#define NPATCH  1024
#define NQ      100
#define NTOK    (BATCH*SEQ)       // 8992
#define H3      3072
#define FHID    4096
#define ATTNSCALE 0.125f
#define NEG_INF_V (-1000000000.0f)

typedef __half fp16;

// ---------------- scratch (static device memory; no allocs) ----------------
__device__ __align__(256) fp16  g_xn_hi[(size_t)NTOK*EMB];
__device__ __align__(256) fp16  g_xn_lo[(size_t)NTOK*EMB];
__device__ __align__(256) float g_qkv[(size_t)NTOK*H3];
__device__ __align__(256) fp16  g_ao_hi[(size_t)NTOK*EMB];
__device__ __align__(256) fp16  g_ao_lo[(size_t)NTOK*EMB];
__device__ __align__(256) float g_x1[(size_t)NTOK*EMB];
__device__ __align__(256) fp16  g_hb_hi[(size_t)NTOK*FHID];
__device__ __align__(256) fp16  g_hb_lo[(size_t)NTOK*FHID];
// transposed weights: [N, K], single fp16
__device__ __align__(256) fp16  g_wqkv[(size_t)H3*EMB];
__device__ __align__(256) fp16  g_wproj[(size_t)EMB*EMB];
__device__ __align__(256) fp16  g_wfc1[(size_t)FHID*EMB];
__device__ __align__(256) fp16  g_wfc2[(size_t)EMB*FHID];

// ---------------- helpers ----------------
__device__ __forceinline__ uint32_t smem_u32(const void* p) {
    uint32_t a;
    asm("{ .reg .u64 t; cvta.to.shared.u64 t, %1; cvt.u32.u64 %0, t; }" : "=r"(a) : "l"(p));
    return a;
}

__device__ __forceinline__ void cp16(uint32_t dst, const void* src, int bytes) {
    asm volatile("cp.async.cg.shared.global [%0], [%1], 16, %2;"
                 :: "r"(dst), "l"(src), "r"(bytes) : "memory");
}
#define CP_COMMIT() asm volatile("cp.async.commit_group;" ::: "memory")
#define CP_WAIT1()  asm volatile("cp.async.wait_group 1;" ::: "memory")

__device__ __forceinline__ void mma_fp16(float* d, const uint32_t* a, const uint32_t* b) {
    asm volatile(
        "mma.sync.aligned.m16n8k16.row.col.f32.f16.f16.f32 "
        "{%0,%1,%2,%3}, {%4,%5,%6,%7}, {%8,%9}, {%0,%1,%2,%3};\n"
        : "+f"(d[0]), "+f"(d[1]), "+f"(d[2]), "+f"(d[3])
        : "r"(a[0]), "r"(a[1]), "r"(a[2]), "r"(a[3]), "r"(b[0]), "r"(b[1]));
}

__device__ __forceinline__ void split_fp16(float x, fp16& h, fp16& l) {
    h = __float2half_rn(x);
    l = __float2half_rn(x - __half2float(h));
}

// ---------------- block reduction (sum, sumsq) ----------------
__device__ __forceinline__ void blockReduce2(float &a, float &b) {
    __shared__ float sa[8], sb[8];
    int lane = threadIdx.x & 31, w = threadIdx.x >> 5;
    #pragma unroll
    for (int o = 16; o; o >>= 1) {
        a += __shfl_xor_sync(0xffffffffu, a, o);
        b += __shfl_xor_sync(0xffffffffu, b, o);
    }
    if (lane == 0) { sa[w] = a; sb[w] = b; }
    __syncthreads();
    if (w == 0) {
        float ra = (lane < 8) ? sa[lane] : 0.f;
        float rb = (lane < 8) ? sb[lane] : 0.f;
        #pragma unroll
        for (int o = 4; o; o >>= 1) {
            ra += __shfl_xor_sync(0xffffffffu, ra, o);
            rb += __shfl_xor_sync(0xffffffffu, rb, o);
        }
        if (lane == 0) { sa[0] = ra; sb[0] = rb; }
    }
    __syncthreads();
    a = sa[0]; b = sb[0];
}

// ---------------- LayerNorm -> hi/lo fp16 ----------------
__global__ void ln_kernel(const float* __restrict__ x, const float* __restrict__ g,
                          const float* __restrict__ be,
                          fp16* __restrict__ ohi, fp16* __restrict__ olo) {
    const int row = blockIdx.x, tid = threadIdx.x;
    const float* xr = x + (size_t)row * EMB;
    float v[4];
    float s = 0.f, sq = 0.f;
    #pragma unroll
    for (int i = 0; i < 4; i++) {
        float t = xr[tid + i * 256];
        v[i] = t; s += t; sq += t * t;
    }
    blockReduce2(s, sq);
    const float m   = s * (1.0f / EMB);
    const float var = sq * (1.0f / EMB) - m * m;
    const float inv = rsqrtf(var + 1e-6f);
    #pragma unroll
    for (int i = 0; i < 4; i++) {
        int c = tid + i * 256;
        float o = (v[i] - m) * inv * g[c] + be[c];
        fp16 h, l; split_fp16(o, h, l);
        ohi[(size_t)row * EMB + c] = h;
        olo[(size_t)row * EMB + c] = l;
    }
}

// ---------------- weight transpose: W[K,N] f32 -> T[N,K] fp16 ----------------
__global__ void wconv_kernel(const float* __restrict__ W, int K, int N,
                             fp16* __restrict__ T) {
    __shared__ float t[32][33];
    const int k0 = blockIdx.y * 32, n0 = blockIdx.x * 32;
    const int tx = threadIdx.x, ty = threadIdx.y;
    #pragma unroll
    for (int i = 0; i < 4; i++)
        t[ty + i * 8][tx] = W[(size_t)(k0 + ty + i * 8) * N + n0 + tx];
    __syncthreads();
    #pragma unroll
    for (int i = 0; i < 4; i++) {
        int n = ty + i * 8;
        T[(size_t)(n0 + n) * K + k0 + tx] = __float2half_rn(t[tx][n]);
    }
}

// ---------------- fp16 mma.sync GEMM, activation hi/lo compensated ----------------
// C[M,N] = A[M,K] @ B^T, A [M,K] hi/lo fp16, B stored [N,K] fp16.
// Block tile 128x128, K-chunk 32, 256 thr, warp grid 4x2, warp tile 32x64.
// cp.async double-buffered. SMEM word layout: [row][kk] packed fp16x2,
// row stride 20 words (16 used + 4 pad -> conflict-free fragment loads).
// EPI: 0 = f32 C; 1 = +bias +resid f32 C; 2 = +bias +GELU -> hi/lo fp16.
#define ST_A_HI  0
#define ST_A_LO  10240
#define ST_B     20480
#define ST_STAGE 30720
#define GEMM_SMEM_BYTES (2 * ST_STAGE)   // 61440

template<int EPI>
__global__ void __launch_bounds__(256, 2)
gemm_mma(const fp16* __restrict__ Ah, const fp16* __restrict__ Al, int lda,
         const fp16* __restrict__ B, int K,
         float* __restrict__ C, int ldc, int M,
         const float* __restrict__ bias,
         const float* __restrict__ resid, int ldr,
         fp16* __restrict__ Ohi, fp16* __restrict__ Olo) {
    extern __shared__ char smem[];
    const uint32_t sbase = smem_u32(smem);

    const int tid    = threadIdx.x;
    const int warp   = tid >> 5;
    const int lane   = tid & 31;
    const int g      = lane >> 2;
    const int t      = lane & 3;
    const int warp_m = warp & 3;
    const int warp_n = warp >> 2;
    const int row0   = blockIdx.y * 128;
    const int col0   = blockIdx.x * 128;

    const int m_   = tid >> 2;          // 0..63 (+64 on iter 1)
    const int q_   = tid & 3;           // 16B quad within 32-k row

    float acc[2][8][4];
    #pragma unroll
    for (int mt = 0; mt < 2; mt++)
        #pragma unroll
        for (int nt = 0; nt < 8; nt++)
            #pragma unroll
            for (int i = 0; i < 4; i++) acc[mt][nt][i] = 0.f;

    const int nch = K >> 5;

    auto issue = [&](int c, int s) {
        const int k0 = c << 5;
        const uint32_t sb = sbase + s * ST_STAGE;
        #pragma unroll
        for (int i = 0; i < 2; i++) {
            const int m = m_ + i * 64;
            const uint32_t d = sb + m * 80 + q_ * 16;
            const int gr = row0 + m;
            const int ok = (gr < M) ? 16 : 0;
            const size_t aoff = (size_t)(ok ? gr : 0) * lda + k0 + q_ * 8;
            cp16(d + ST_A_HI, Ah + aoff, ok);
            cp16(d + ST_A_LO, Al + aoff, ok);
            const size_t boff = (size_t)(col0 + m) * K + k0 + q_ * 8;
            cp16(d + ST_B, B + boff, 16);
        }
    };

    issue(0, 0);
    CP_COMMIT();

    for (int c = 0; c < nch; ++c) {
        const int s = c & 1;
        if (c + 1 < nch) issue(c + 1, s ^ 1);
        CP_COMMIT();
        CP_WAIT1();
        __syncthreads();

        const uint32_t* sAh = (const uint32_t*)(smem + s * ST_STAGE + ST_A_HI);
        const uint32_t* sAl = (const uint32_t*)(smem + s * ST_STAGE + ST_A_LO);
        const uint32_t* sB  = (const uint32_t*)(smem + s * ST_STAGE + ST_B);

        #pragma unroll
        for (int ks = 0; ks < 2; ++ks) {
            const int kw = ks * 8;
            uint32_t ah[2][4], al[2][4];
            #pragma unroll
            for (int mt = 0; mt < 2; mt++) {
                const int r = warp_m * 32 + mt * 16 + g;
                ah[mt][0] = sAh[r       * 20 + kw + t];
                ah[mt][1] = sAh[(r + 8) * 20 + kw + t];
                ah[mt][2] = sAh[r       * 20 + kw + t + 4];
                ah[mt][3] = sAh[(r + 8) * 20 + kw + t + 4];
                al[mt][0] = sAl[r       * 20 + kw + t];
                al[mt][1] = sAl[(r + 8) * 20 + kw + t];
                al[mt][2] = sAl[r       * 20 + kw + t + 4];
                al[mt][3] = sAl[(r + 8) * 20 + kw + t + 4];
            }
            #pragma unroll
            for (int nt = 0; nt < 8; nt++) {
                const int n = warp_n * 64 + nt * 8 + g;
                uint32_t bh[2];
                bh[0] = sB[n * 20 + kw + t];
                bh[1] = sB[n * 20 + kw + t + 4];
                #pragma unroll
                for (int mt = 0; mt < 2; mt++) {
                    mma_fp16(acc[mt][nt], ah[mt], bh);   // hi*B
                    mma_fp16(acc[mt][nt], al[mt], bh);   // lo*B
                }
            }
        }
        __syncthreads();
    }

    // epilogue: c0={g,2t} c1={g,2t+1} c2={g+8,2t} c3={g+8,2t+1}
    #pragma unroll
    for (int mt = 0; mt < 2; mt++) {
        #pragma unroll
        for (int nt = 0; nt < 8; nt++) {
            #pragma unroll
            for (int i = 0; i < 4; i++) {
                const int gr = row0 + warp_m * 32 + mt * 16 + g + ((i >> 1) ? 8 : 0);
                const int gc = col0 + warp_n * 64 + nt * 8 + 2 * t + (i & 1);
                if (gr >= M) continue;
                float v = acc[mt][nt][i];
                if (EPI >= 1) v += bias[gc];
                if (EPI == 1) {
                    v += resid[(size_t)gr * ldr + gc];
                    C[(size_t)gr * ldc + gc] = v;
                } else if (EPI == 2) {
                    v = 0.5f * v * (1.0f + erff(v * 0.70710678118654752f));
                    fp16 h, l; split_fp16(v, h, l);
                    Ohi[(size_t)gr * ldc + gc] = h;
                    Olo[(size_t)gr * ldc + gc] = l;
                } else {
                    C[(size_t)gr * ldc + gc] = v;
                }
            }
        }
    }
}

// ---------------- fused flash-style attention (epilogue -> hi/lo fp16) ------------
__global__ void attn_kernel(const float* __restrict__ qkv,
                            const float* __restrict__ mask,
                            fp16* __restrict__ ohi, fp16* __restrict__ olo) {
    const int z = blockIdx.y, b = z >> 4, h = z & 15;
    const int i0 = blockIdx.x * 64;

    __shared__ float Qt[64][65];
    __shared__ float KV[64 * 33];
    __shared__ float Ps[64 * 33];

    const int tid  = threadIdx.x;
    const int trow = tid >> 3;
    const int tcol = tid & 7;
    const int rb   = trow * 2;
    const int cb   = tcol * 4;
    const int oc   = tcol * 8;

    const float* qbase = qkv + (size_t)b * SEQ * H3 + (size_t)h * HDIM;
    const float* kbase = qbase + EMB;
    const float* vbase = qbase + 2 * EMB;

    #pragma unroll
    for (int it = 0; it < 16; ++it) {
        int idx = tid + it * 256;
        int r = idx >> 6, c = idx & 63;
        int gi = i0 + r;
        Qt[c][r] = (gi < SEQ) ? qbase[(size_t)gi * H3 + c] : 0.f;
    }

    const int gi[2] = { i0 + rb, i0 + rb + 1 };
    const bool isq[2] = { gi[0] >= NPATCH && gi[0] < SEQ, gi[1] >= NPATCH && gi[1] < SEQ };
    const float* mrowp[2];
    mrowp[0] = isq[0] ? mask + ((size_t)b * NQ + (size_t)(gi[0] - NPATCH)) * NPATCH : mask;
    mrowp[1] = isq[1] ? mask + ((size_t)b * NQ + (size_t)(gi[1] - NPATCH)) * NPATCH : mask;

    float mrun[2] = { -3.0e38f, -3.0e38f };
    float lrun[2] = { 0.f, 0.f };
    float acc[2][8];
    #pragma unroll
    for (int i = 0; i < 2; i++)
        #pragma unroll
        for (int j = 0; j < 8; j++) acc[i][j] = 0.f;

    for (int j0 = 0; j0 < SEQ; j0 += 32) {
        __syncthreads();
        #pragma unroll
        for (int it = 0; it < 8; ++it) {
            int idx = tid + it * 256;
            int j = idx >> 6, c = idx & 63;
            int gj = j0 + j;
            KV[c * 33 + j] = (gj < SEQ) ? kbase[(size_t)gj * H3 + c] : 0.f;
        }
        __syncthreads();

        float s[2][4] = {{0.f,0.f,0.f,0.f},{0.f,0.f,0.f,0.f}};
        #pragma unroll
        for (int d = 0; d < 64; d++) {
            float a0 = Qt[d][rb], a1 = Qt[d][rb + 1];
            #pragma unroll
            for (int j = 0; j < 4; j++) {
                float kk = KV[d * 33 + cb + j];
                s[0][j] += a0 * kk;
                s[1][j] += a1 * kk;
            }
        }

        #pragma unroll
        for (int i = 0; i < 2; i++) {
            #pragma unroll
            for (int j = 0; j < 4; j++) {
                int gj = j0 + cb + j;
                float v = s[i][j] * ATTNSCALE;
                if (gj >= SEQ) v = -3.0e38f;
                else if (isq[i] && gj < NPATCH && mrowp[i][gj] <= 0.5f) v = NEG_INF_V;
                s[i][j] = v;
            }
        }

        #pragma unroll
        for (int i = 0; i < 2; i++) {
            float mx = fmaxf(fmaxf(s[i][0], s[i][1]), fmaxf(s[i][2], s[i][3]));
            #pragma unroll
            for (int o = 1; o < 8; o <<= 1)
                mx = fmaxf(mx, __shfl_xor_sync(0xffffffffu, mx, o));
            float mnew = fmaxf(mrun[i], mx);
            float corr = expf(mrun[i] - mnew);
            mrun[i] = mnew;
            lrun[i] *= corr;
            #pragma unroll
            for (int j = 0; j < 8; j++) acc[i][j] *= corr;
            float sum = 0.f;
            #pragma unroll
            for (int j = 0; j < 4; j++) {
                float p = expf(s[i][j] - mnew);
                s[i][j] = p;
                sum += p;
            }
            #pragma unroll
            for (int o = 1; o < 8; o <<= 1)
                sum += __shfl_xor_sync(0xffffffffu, sum, o);
            lrun[i] += sum;
        }

        #pragma unroll
        for (int i = 0; i < 2; i++)
            #pragma unroll
            for (int j = 0; j < 4; j++)
                Ps[(rb + i) * 33 + cb + j] = s[i][j];
        __syncthreads();

        #pragma unroll
        for (int it = 0; it < 8; ++it) {
            int idx = tid + it * 256;
            int k = idx >> 6, c = idx & 63;
            int gk = j0 + k;
            KV[k * 65 + c] = (gk < SEQ) ? vbase[(size_t)gk * H3 + c] : 0.f;
        }
        __syncthreads();

        #pragma unroll 8
        for (int k = 0; k < 32; k++) {
            float p0 = Ps[rb * 33 + k];
            float p1 = Ps[(rb + 1) * 33 + k];
            #pragma unroll
            for (int j = 0; j < 8; j++) {
                float vv = KV[k * 65 + oc + j];
                acc[0][j] += p0 * vv;
                acc[1][j] += p1 * vv;
            }
        }
    }

    #pragma unroll
    for (int i = 0; i < 2; i++) {
        if (gi[i] < SEQ) {
            float inv = 1.0f / lrun[i];
            size_t base = (size_t)b * SEQ * EMB + (size_t)gi[i] * EMB + (size_t)h * HDIM;
            #pragma unroll
            for (int j = 0; j < 8; j++) {
                float v = acc[i][j] * inv;
                fp16 hh, ll; split_fp16(v, hh, ll);
                ohi[base + oc + j] = hh;
                olo[base + oc + j] = ll;
            }
        }
    }
}

// ---------------- launch ----------------
extern "C" void kernel_launch(void* const* d_in, const int* in_sizes, int n_in,
                              void* d_out, int out_size) {
    (void)in_sizes; (void)n_in; (void)out_size;
    const float* x      = (const float*)d_in[0];
    const float* mask   = (const float*)d_in[1];
    const float* qkv_w  = (const float*)d_in[2];
    const float* proj_w = (const float*)d_in[3];
    const float* proj_b = (const float*)d_in[4];
    const float* ln1_g  = (const float*)d_in[5];
    const float* ln1_b  = (const float*)d_in[6];
    const float* ln2_g  = (const float*)d_in[7];
    const float* ln2_b  = (const float*)d_in[8];
    const float* fc1_w  = (const float*)d_in[9];
    const float* fc1_b  = (const float*)d_in[10];
    const float* fc2_w  = (const float*)d_in[11];
    const float* fc2_b  = (const float*)d_in[12];
    float* out = (float*)d_out;

    fp16 *xnh, *xnl, *aoh, *aol, *hbh, *hbl;
    fp16 *wq, *wp, *w1, *w2;
    float *qkvb, *x1;
    cudaGetSymbolAddress((void**)&xnh, g_xn_hi);  cudaGetSymbolAddress((void**)&xnl, g_xn_lo);
    cudaGetSymbolAddress((void**)&aoh, g_ao_hi);  cudaGetSymbolAddress((void**)&aol, g_ao_lo);
    cudaGetSymbolAddress((void**)&hbh, g_hb_hi);  cudaGetSymbolAddress((void**)&hbl, g_hb_lo);
    cudaGetSymbolAddress((void**)&wq, g_wqkv);
    cudaGetSymbolAddress((void**)&wp, g_wproj);
    cudaGetSymbolAddress((void**)&w1, g_wfc1);
    cudaGetSymbolAddress((void**)&w2, g_wfc2);
    cudaGetSymbolAddress((void**)&qkvb, g_qkv);
    cudaGetSymbolAddress((void**)&x1, g_x1);

    cudaFuncSetAttribute(gemm_mma<0>, cudaFuncAttributeMaxDynamicSharedMemorySize, GEMM_SMEM_BYTES);
    cudaFuncSetAttribute(gemm_mma<1>, cudaFuncAttributeMaxDynamicSharedMemorySize, GEMM_SMEM_BYTES);
    cudaFuncSetAttribute(gemm_mma<2>, cudaFuncAttributeMaxDynamicSharedMemorySize, GEMM_SMEM_BYTES);

    const dim3 wblk(32, 8);
    const int MB = (NTOK + 127) / 128;  // 71

    // weight transpose + fp16 convert
    wconv_kernel<<<dim3(H3/32,  EMB/32),  wblk>>>(qkv_w,  EMB,  H3,   wq);
    wconv_kernel<<<dim3(EMB/32, EMB/32),  wblk>>>(proj_w, EMB,  EMB,  wp);
    wconv_kernel<<<dim3(FHID/32,EMB/32),  wblk>>>(fc1_w,  EMB,  FHID, w1);
    wconv_kernel<<<dim3(EMB/32, FHID/32), wblk>>>(fc2_w,  FHID, EMB,  w2);

    // 1. LN1 -> hi/lo
    ln_kernel<<<NTOK, 256>>>(x, ln1_g, ln1_b, xnh, xnl);
    // 2. QKV = xn @ qkv_w -> f32
    gemm_mma<0><<<dim3(H3/128, MB), 256, GEMM_SMEM_BYTES>>>(
        xnh, xnl, EMB, wq, EMB, qkvb, H3, NTOK, nullptr, nullptr, 0, nullptr, nullptr);
    // 3. fused attention -> hi/lo
    attn_kernel<<<dim3(18, BATCH * NHEAD), 256>>>(qkvb, mask, aoh, aol);
    // 4. x1 = ao @ proj_w + b + x
    gemm_mma<1><<<dim3(EMB/128, MB), 256, GEMM_SMEM_BYTES>>>(
        aoh, aol, EMB, wp, EMB, x1, EMB, NTOK, proj_b, x, EMB, nullptr, nullptr);
    // 5. LN2 -> hi/lo
    ln_kernel<<<NTOK, 256>>>(x1, ln2_g, ln2_b, xnh, xnl);
    // 6. hb = gelu(xn @ fc1_w + b) -> hi/lo
    gemm_mma<2><<<dim3(FHID/128, MB), 256, GEMM_SMEM_BYTES>>>(
        xnh, xnl, EMB, w1, EMB, nullptr, FHID, NTOK, fc1_b, nullptr, 0, hbh, hbl);
    // 7. out = hb @ fc2_w + b + x1
    gemm_mma<1><<<dim3(EMB/128, MB), 256, GEMM_SMEM_BYTES>>>(
        hbh, hbl, FHID, w2, FHID, out, EMB, NTOK, fc2_b, x1, EMB, nullptr, nullptr);
}

// round 9
// speedup vs baseline: 4.0641x; 2.0314x over previous
#include <cuda_runtime.h>
#include <cuda_fp16.h>
#include <math.h>
#include <stdint.h>

// ---------------- problem constants ----------------
#define BATCH   8
#define SEQ     1124
#define EMB     1024
#define NHEAD   16
#define HDIM    64
#define NPATCH  1024
#define NQ      100
#define NTOK    (BATCH*SEQ)       // 8992
#define H3      3072
#define FHID    4096
#define ATTNSCALE 0.125f
#define NEG_INF_V (-1000000000.0f)

typedef __half fp16;

// ---------------- scratch (static device memory; no allocs) ----------------
__device__ __align__(256) fp16  g_xn_hi[(size_t)NTOK*EMB];
__device__ __align__(256) fp16  g_xn_lo[(size_t)NTOK*EMB];
__device__ __align__(256) fp16  g_qkvh[(size_t)NTOK*H3];     // fp16 qkv (single)
__device__ __align__(256) fp16  g_ao_hi[(size_t)NTOK*EMB];
__device__ __align__(256) fp16  g_ao_lo[(size_t)NTOK*EMB];
__device__ __align__(256) float g_x1[(size_t)NTOK*EMB];
__device__ __align__(256) fp16  g_hb_hi[(size_t)NTOK*FHID];
__device__ __align__(256) fp16  g_hb_lo[(size_t)NTOK*FHID];
// transposed weights: [N, K], single fp16
__device__ __align__(256) fp16  g_wqkv[(size_t)H3*EMB];
__device__ __align__(256) fp16  g_wproj[(size_t)EMB*EMB];
__device__ __align__(256) fp16  g_wfc1[(size_t)FHID*EMB];
__device__ __align__(256) fp16  g_wfc2[(size_t)EMB*FHID];

// ---------------- helpers ----------------
__device__ __forceinline__ uint32_t smem_u32(const void* p) {
    uint32_t a;
    asm("{ .reg .u64 t; cvta.to.shared.u64 t, %1; cvt.u32.u64 %0, t; }" : "=r"(a) : "l"(p));
    return a;
}

__device__ __forceinline__ void cp16(uint32_t dst, const void* src, int bytes) {
    asm volatile("cp.async.cg.shared.global [%0], [%1], 16, %2;"
                 :: "r"(dst), "l"(src), "r"(bytes) : "memory");
}
#define CP_COMMIT() asm volatile("cp.async.commit_group;" ::: "memory")
#define CP_WAIT1()  asm volatile("cp.async.wait_group 1;" ::: "memory")

__device__ __forceinline__ void mma_fp16(float* d, const uint32_t* a, const uint32_t* b) {
    asm volatile(
        "mma.sync.aligned.m16n8k16.row.col.f32.f16.f16.f32 "
        "{%0,%1,%2,%3}, {%4,%5,%6,%7}, {%8,%9}, {%0,%1,%2,%3};\n"
        : "+f"(d[0]), "+f"(d[1]), "+f"(d[2]), "+f"(d[3])
        : "r"(a[0]), "r"(a[1]), "r"(a[2]), "r"(a[3]), "r"(b[0]), "r"(b[1]));
}

__device__ __forceinline__ void ldmx4t(uint32_t& r0, uint32_t& r1, uint32_t& r2,
                                       uint32_t& r3, uint32_t addr) {
    asm volatile("ldmatrix.sync.aligned.m8n8.x4.trans.shared.b16 {%0,%1,%2,%3}, [%4];"
                 : "=r"(r0), "=r"(r1), "=r"(r2), "=r"(r3) : "r"(addr));
}

__device__ __forceinline__ uint32_t pack2(float a, float b) {
    __half2 p = __floats2half2_rn(a, b);
    return *(uint32_t*)&p;
}

__device__ __forceinline__ void split_fp16(float x, fp16& h, fp16& l) {
    h = __float2half_rn(x);
    l = __float2half_rn(x - __half2float(h));
}

// ---------------- block reduction (sum, sumsq) ----------------
__device__ __forceinline__ void blockReduce2(float &a, float &b) {
    __shared__ float sa[8], sb[8];
    int lane = threadIdx.x & 31, w = threadIdx.x >> 5;
    #pragma unroll
    for (int o = 16; o; o >>= 1) {
        a += __shfl_xor_sync(0xffffffffu, a, o);
        b += __shfl_xor_sync(0xffffffffu, b, o);
    }
    if (lane == 0) { sa[w] = a; sb[w] = b; }
    __syncthreads();
    if (w == 0) {
        float ra = (lane < 8) ? sa[lane] : 0.f;
        float rb = (lane < 8) ? sb[lane] : 0.f;
        #pragma unroll
        for (int o = 4; o; o >>= 1) {
            ra += __shfl_xor_sync(0xffffffffu, ra, o);
            rb += __shfl_xor_sync(0xffffffffu, rb, o);
        }
        if (lane == 0) { sa[0] = ra; sb[0] = rb; }
    }
    __syncthreads();
    a = sa[0]; b = sb[0];
}

// ---------------- LayerNorm -> hi/lo fp16 ----------------
__global__ void ln_kernel(const float* __restrict__ x, const float* __restrict__ g,
                          const float* __restrict__ be,
                          fp16* __restrict__ ohi, fp16* __restrict__ olo) {
    const int row = blockIdx.x, tid = threadIdx.x;
    const float* xr = x + (size_t)row * EMB;
    float v[4];
    float s = 0.f, sq = 0.f;
    #pragma unroll
    for (int i = 0; i < 4; i++) {
        float t = xr[tid + i * 256];
        v[i] = t; s += t; sq += t * t;
    }
    blockReduce2(s, sq);
    const float m   = s * (1.0f / EMB);
    const float var = sq * (1.0f / EMB) - m * m;
    const float inv = rsqrtf(var + 1e-6f);
    #pragma unroll
    for (int i = 0; i < 4; i++) {
        int c = tid + i * 256;
        float o = (v[i] - m) * inv * g[c] + be[c];
        fp16 h, l; split_fp16(o, h, l);
        ohi[(size_t)row * EMB + c] = h;
        olo[(size_t)row * EMB + c] = l;
    }
}

// ---------------- weight transpose: W[K,N] f32 -> T[N,K] fp16 ----------------
__global__ void wconv_kernel(const float* __restrict__ W, int K, int N,
                             fp16* __restrict__ T) {
    __shared__ float t[32][33];
    const int k0 = blockIdx.y * 32, n0 = blockIdx.x * 32;
    const int tx = threadIdx.x, ty = threadIdx.y;
    #pragma unroll
    for (int i = 0; i < 4; i++)
        t[ty + i * 8][tx] = W[(size_t)(k0 + ty + i * 8) * N + n0 + tx];
    __syncthreads();
    #pragma unroll
    for (int i = 0; i < 4; i++) {
        int n = ty + i * 8;
        T[(size_t)(n0 + n) * K + k0 + tx] = __float2half_rn(t[tx][n]);
    }
}

// ---------------- fp16 mma.sync GEMM, activation hi/lo compensated ----------------
// C[M,N] = A[M,K] @ B^T, A [M,K] hi/lo fp16, B stored [N,K] fp16.
// EPI: 0 = f32 C; 1 = +bias +resid f32 C; 2 = +bias +GELU -> hi/lo fp16;
//      3 = plain -> single fp16 (qkv).
#define ST_A_HI  0
#define ST_A_LO  10240
#define ST_B     20480
#define ST_STAGE 30720
#define GEMM_SMEM_BYTES (2 * ST_STAGE)   // 61440

template<int EPI>
__global__ void __launch_bounds__(256, 2)
gemm_mma(const fp16* __restrict__ Ah, const fp16* __restrict__ Al, int lda,
         const fp16* __restrict__ B, int K,
         float* __restrict__ C, int ldc, int M,
         const float* __restrict__ bias,
         const float* __restrict__ resid, int ldr,
         fp16* __restrict__ Ohi, fp16* __restrict__ Olo) {
    extern __shared__ char smem[];
    const uint32_t sbase = smem_u32(smem);

    const int tid    = threadIdx.x;
    const int warp   = tid >> 5;
    const int lane   = tid & 31;
    const int g      = lane >> 2;
    const int t      = lane & 3;
    const int warp_m = warp & 3;
    const int warp_n = warp >> 2;
    const int row0   = blockIdx.y * 128;
    const int col0   = blockIdx.x * 128;

    const int m_   = tid >> 2;
    const int q_   = tid & 3;

    float acc[2][8][4];
    #pragma unroll
    for (int mt = 0; mt < 2; mt++)
        #pragma unroll
        for (int nt = 0; nt < 8; nt++)
            #pragma unroll
            for (int i = 0; i < 4; i++) acc[mt][nt][i] = 0.f;

    const int nch = K >> 5;

    auto issue = [&](int c, int s) {
        const int k0 = c << 5;
        const uint32_t sb = sbase + s * ST_STAGE;
        #pragma unroll
        for (int i = 0; i < 2; i++) {
            const int m = m_ + i * 64;
            const uint32_t d = sb + m * 80 + q_ * 16;
            const int gr = row0 + m;
            const int ok = (gr < M) ? 16 : 0;
            const size_t aoff = (size_t)(ok ? gr : 0) * lda + k0 + q_ * 8;
            cp16(d + ST_A_HI, Ah + aoff, ok);
            cp16(d + ST_A_LO, Al + aoff, ok);
            const size_t boff = (size_t)(col0 + m) * K + k0 + q_ * 8;
            cp16(d + ST_B, B + boff, 16);
        }
    };

    issue(0, 0);
    CP_COMMIT();

    for (int c = 0; c < nch; ++c) {
        const int s = c & 1;
        if (c + 1 < nch) issue(c + 1, s ^ 1);
        CP_COMMIT();
        CP_WAIT1();
        __syncthreads();

        const uint32_t* sAh = (const uint32_t*)(smem + s * ST_STAGE + ST_A_HI);
        const uint32_t* sAl = (const uint32_t*)(smem + s * ST_STAGE + ST_A_LO);
        const uint32_t* sB  = (const uint32_t*)(smem + s * ST_STAGE + ST_B);

        #pragma unroll
        for (int ks = 0; ks < 2; ++ks) {
            const int kw = ks * 8;
            uint32_t ah[2][4], al[2][4];
            #pragma unroll
            for (int mt = 0; mt < 2; mt++) {
                const int r = warp_m * 32 + mt * 16 + g;
                ah[mt][0] = sAh[r       * 20 + kw + t];
                ah[mt][1] = sAh[(r + 8) * 20 + kw + t];
                ah[mt][2] = sAh[r       * 20 + kw + t + 4];
                ah[mt][3] = sAh[(r + 8) * 20 + kw + t + 4];
                al[mt][0] = sAl[r       * 20 + kw + t];
                al[mt][1] = sAl[(r + 8) * 20 + kw + t];
                al[mt][2] = sAl[r       * 20 + kw + t + 4];
                al[mt][3] = sAl[(r + 8) * 20 + kw + t + 4];
            }
            #pragma unroll
            for (int nt = 0; nt < 8; nt++) {
                const int n = warp_n * 64 + nt * 8 + g;
                uint32_t bh[2];
                bh[0] = sB[n * 20 + kw + t];
                bh[1] = sB[n * 20 + kw + t + 4];
                #pragma unroll
                for (int mt = 0; mt < 2; mt++) {
                    mma_fp16(acc[mt][nt], ah[mt], bh);   // hi*B
                    mma_fp16(acc[mt][nt], al[mt], bh);   // lo*B
                }
            }
        }
        __syncthreads();
    }

    #pragma unroll
    for (int mt = 0; mt < 2; mt++) {
        #pragma unroll
        for (int nt = 0; nt < 8; nt++) {
            #pragma unroll
            for (int i = 0; i < 4; i++) {
                const int gr = row0 + warp_m * 32 + mt * 16 + g + ((i >> 1) ? 8 : 0);
                const int gc = col0 + warp_n * 64 + nt * 8 + 2 * t + (i & 1);
                if (gr >= M) continue;
                float v = acc[mt][nt][i];
                if (EPI == 1 || EPI == 2) v += bias[gc];
                if (EPI == 1) {
                    v += resid[(size_t)gr * ldr + gc];
                    C[(size_t)gr * ldc + gc] = v;
                } else if (EPI == 2) {
                    v = 0.5f * v * (1.0f + erff(v * 0.70710678118654752f));
                    fp16 h, l; split_fp16(v, h, l);
                    Ohi[(size_t)gr * ldc + gc] = h;
                    Olo[(size_t)gr * ldc + gc] = l;
                } else if (EPI == 3) {
                    Ohi[(size_t)gr * ldc + gc] = __float2half_rn(v);
                } else {
                    C[(size_t)gr * ldc + gc] = v;
                }
            }
        }
    }
}

// ---------------- tensor-core flash attention ----------------
// grid (18, 128): x = 64-query tile, y = b*16+h. 128 threads (4 warps, 16 rows each).
// SMEM rows: 64 halves data + pad -> 36 words (144 B) per row.
#define AT_ROW_B  144
#define AT_MATB   (64 * AT_ROW_B)      // 9216
#define AT_Q      0
#define AT_STAGES AT_MATB              // K/V stages start
#define AT_K      0
#define AT_V      AT_MATB
#define AT_STAGE_B (2 * AT_MATB)       // 18432
#define ATTN_SMEM (AT_MATB + 2 * AT_STAGE_B)   // 46080

__global__ void __launch_bounds__(128)
attn_mma_kernel(const fp16* __restrict__ qkvh, const float* __restrict__ mask,
                fp16* __restrict__ ohi, fp16* __restrict__ olo) {
    extern __shared__ char smem[];
    const uint32_t sb = smem_u32(smem);
    const int z = blockIdx.y, b = z >> 4, h = z & 15;
    const int i0 = blockIdx.x * 64;
    const int tid = threadIdx.x, w = tid >> 5, lane = tid & 31;
    const int g = lane >> 2, t = lane & 3;

    const fp16* Qg = qkvh + (size_t)b * SEQ * H3 + h * HDIM;
    const fp16* Kg = Qg + EMB;
    const fp16* Vg = Qg + 2 * EMB;

    // async load Q tile (rows 64 x 64 halves)
    #pragma unroll
    for (int i = 0; i < 4; i++) {
        int idx = tid + i * 128;
        int r = idx >> 3, q = idx & 7;
        int gr = i0 + r;
        int ok = (gr < SEQ) ? 16 : 0;
        cp16(sb + AT_Q + r * AT_ROW_B + q * 16,
             Qg + (size_t)(ok ? gr : 0) * H3 + q * 8, ok);
    }
    auto issueKV = [&](int c, int s) {
        const int j0 = c * 64;
        const uint32_t st = sb + AT_STAGES + s * AT_STAGE_B;
        #pragma unroll
        for (int i = 0; i < 4; i++) {
            int idx = tid + i * 128;
            int r = idx >> 3, q = idx & 7;
            int gk = j0 + r;
            int ok = (gk < SEQ) ? 16 : 0;
            const size_t off = (size_t)(ok ? gk : 0) * H3 + q * 8;
            cp16(st + AT_K + r * AT_ROW_B + q * 16, Kg + off, ok);
            cp16(st + AT_V + r * AT_ROW_B + q * 16, Vg + off, ok);
        }
    };
    issueKV(0, 0);
    CP_COMMIT();   // group: Q + tile0

    const int row0 = i0 + w * 16 + g;
    const int row1 = row0 + 8;
    const bool isq0 = (row0 >= NPATCH) && (row0 < SEQ);
    const bool isq1 = (row1 >= NPATCH) && (row1 < SEQ);
    const float* mr0 = mask + ((size_t)b * NQ + (size_t)(isq0 ? row0 - NPATCH : 0)) * NPATCH;
    const float* mr1 = mask + ((size_t)b * NQ + (size_t)(isq1 ? row1 - NPATCH : 0)) * NPATCH;

    float m0 = -3.0e38f, m1 = -3.0e38f, l0 = 0.f, l1 = 0.f;
    float O[8][4];
    #pragma unroll
    for (int j = 0; j < 8; j++)
        #pragma unroll
        for (int i = 0; i < 4; i++) O[j][i] = 0.f;
    uint32_t qf[4][4];

    const int NT = (SEQ + 63) / 64;   // 18
    for (int c = 0; c < NT; c++) {
        const int s = c & 1;
        if (c + 1 < NT) issueKV(c + 1, s ^ 1);
        CP_COMMIT();
        CP_WAIT1();
        __syncthreads();

        const uint32_t* sK = (const uint32_t*)(smem + AT_STAGES + s * AT_STAGE_B + AT_K);
        const uint32_t vbase = sb + AT_STAGES + s * AT_STAGE_B + AT_V;

        if (c == 0) {   // Q fragments, register-resident for the whole kernel
            const uint32_t* sQ = (const uint32_t*)(smem + AT_Q);
            const int r = w * 16 + g;
            #pragma unroll
            for (int kb = 0; kb < 4; kb++) {
                qf[kb][0] = sQ[r       * 36 + kb * 8 + t];
                qf[kb][1] = sQ[(r + 8) * 36 + kb * 8 + t];
                qf[kb][2] = sQ[r       * 36 + kb * 8 + t + 4];
                qf[kb][3] = sQ[(r + 8) * 36 + kb * 8 + t + 4];
            }
        }

        // ---- S = Q K^T (16 rows x 64 keys per warp) ----
        float sc[8][4];
        #pragma unroll
        for (int j = 0; j < 8; j++)
            #pragma unroll
            for (int i = 0; i < 4; i++) sc[j][i] = 0.f;
        #pragma unroll
        for (int j = 0; j < 8; j++) {
            const int kr = 8 * j + g;
            #pragma unroll
            for (int kb = 0; kb < 4; kb++) {
                uint32_t bf[2];
                bf[0] = sK[kr * 36 + kb * 8 + t];
                bf[1] = sK[kr * 36 + kb * 8 + t + 4];
                mma_fp16(sc[j], qf[kb], bf);
            }
        }

        // ---- scale + mask ----
        const int j0k = c * 64;
        #pragma unroll
        for (int j = 0; j < 8; j++) {
            const int k0 = j0k + 8 * j + 2 * t;
            #pragma unroll
            for (int i = 0; i < 4; i++) {
                const int key = k0 + (i & 1);
                float v = sc[j][i] * ATTNSCALE;
                if (key >= SEQ) v = -3.0e38f;
                else if ((i < 2) ? isq0 : isq1) {
                    if (key < NPATCH) {
                        const float* mr = (i < 2) ? mr0 : mr1;
                        if (mr[key] <= 0.5f) v = NEG_INF_V;
                    }
                }
                sc[j][i] = v;
            }
        }

        // ---- online softmax (rows owned by 4 lanes: xor 1,2) ----
        float mx0 = -3.0e38f, mx1 = -3.0e38f;
        #pragma unroll
        for (int j = 0; j < 8; j++) {
            mx0 = fmaxf(mx0, fmaxf(sc[j][0], sc[j][1]));
            mx1 = fmaxf(mx1, fmaxf(sc[j][2], sc[j][3]));
        }
        #pragma unroll
        for (int o = 1; o < 4; o <<= 1) {
            mx0 = fmaxf(mx0, __shfl_xor_sync(0xffffffffu, mx0, o));
            mx1 = fmaxf(mx1, __shfl_xor_sync(0xffffffffu, mx1, o));
        }
        const float mn0 = fmaxf(m0, mx0), mn1 = fmaxf(m1, mx1);
        const float cr0 = expf(m0 - mn0), cr1 = expf(m1 - mn1);
        m0 = mn0; m1 = mn1;
        l0 *= cr0; l1 *= cr1;
        #pragma unroll
        for (int j = 0; j < 8; j++) {
            O[j][0] *= cr0; O[j][1] *= cr0;
            O[j][2] *= cr1; O[j][3] *= cr1;
        }
        float s0 = 0.f, s1 = 0.f;
        #pragma unroll
        for (int j = 0; j < 8; j++) {
            sc[j][0] = expf(sc[j][0] - m0); s0 += sc[j][0];
            sc[j][1] = expf(sc[j][1] - m0); s0 += sc[j][1];
            sc[j][2] = expf(sc[j][2] - m1); s1 += sc[j][2];
            sc[j][3] = expf(sc[j][3] - m1); s1 += sc[j][3];
        }
        #pragma unroll
        for (int o = 1; o < 4; o <<= 1) {
            s0 += __shfl_xor_sync(0xffffffffu, s0, o);
            s1 += __shfl_xor_sync(0xffffffffu, s1, o);
        }
        l0 += s0; l1 += s1;

        // ---- O += P V : P C-frag repacked as A-frag; V via ldmatrix.trans ----
        #pragma unroll
        for (int jp = 0; jp < 4; jp++) {        // 16-key blocks
            uint32_t a[4];
            a[0] = pack2(sc[2 * jp][0],     sc[2 * jp][1]);
            a[1] = pack2(sc[2 * jp][2],     sc[2 * jp][3]);
            a[2] = pack2(sc[2 * jp + 1][0], sc[2 * jp + 1][1]);
            a[3] = pack2(sc[2 * jp + 1][2], sc[2 * jp + 1][3]);
            #pragma unroll
            for (int np = 0; np < 4; np++) {    // 16-d column pairs
                const uint32_t addr = vbase
                    + (16 * jp + (lane & 15)) * AT_ROW_B
                    + np * 32 + (lane >> 4) * 16;
                uint32_t v0, v1, v2, v3;
                ldmx4t(v0, v1, v2, v3, addr);
                uint32_t bf0[2] = { v0, v1 };
                uint32_t bf1[2] = { v2, v3 };
                mma_fp16(O[2 * np],     a, bf0);
                mma_fp16(O[2 * np + 1], a, bf1);
            }
        }
        __syncthreads();
    }

    // ---- epilogue: normalize, split hi/lo ----
    const float il0 = 1.0f / l0, il1 = 1.0f / l1;
    const size_t base0 = ((size_t)b * SEQ + (size_t)(row0 < SEQ ? row0 : 0)) * EMB + h * HDIM;
    const size_t base1 = ((size_t)b * SEQ + (size_t)(row1 < SEQ ? row1 : 0)) * EMB + h * HDIM;
    #pragma unroll
    for (int np = 0; np < 8; np++) {
        #pragma unroll
        for (int i = 0; i < 4; i++) {
            const int d = 8 * np + 2 * t + (i & 1);
            const bool okrow = (i < 2) ? (row0 < SEQ) : (row1 < SEQ);
            if (!okrow) continue;
            const float v = O[np][i] * ((i < 2) ? il0 : il1);
            const size_t a = ((i < 2) ? base0 : base1) + d;
            fp16 hh, ll; split_fp16(v, hh, ll);
            ohi[a] = hh; olo[a] = ll;
        }
    }
}

// ---------------- launch ----------------
extern "C" void kernel_launch(void* const* d_in, const int* in_sizes, int n_in,
                              void* d_out, int out_size) {
    (void)in_sizes; (void)n_in; (void)out_size;
    const float* x      = (const float*)d_in[0];
    const float* mask   = (const float*)d_in[1];
    const float* qkv_w  = (const float*)d_in[2];
    const float* proj_w = (const float*)d_in[3];
    const float* proj_b = (const float*)d_in[4];
    const float* ln1_g  = (const float*)d_in[5];
    const float* ln1_b  = (const float*)d_in[6];
    const float* ln2_g  = (const float*)d_in[7];
    const float* ln2_b  = (const float*)d_in[8];
    const float* fc1_w  = (const float*)d_in[9];
    const float* fc1_b  = (const float*)d_in[10];
    const float* fc2_w  = (const float*)d_in[11];
    const float* fc2_b  = (const float*)d_in[12];
    float* out = (float*)d_out;

    fp16 *xnh, *xnl, *aoh, *aol, *hbh, *hbl, *qkvh;
    fp16 *wq, *wp, *w1, *w2;
    float *x1;
    cudaGetSymbolAddress((void**)&xnh, g_xn_hi);  cudaGetSymbolAddress((void**)&xnl, g_xn_lo);
    cudaGetSymbolAddress((void**)&aoh, g_ao_hi);  cudaGetSymbolAddress((void**)&aol, g_ao_lo);
    cudaGetSymbolAddress((void**)&hbh, g_hb_hi);  cudaGetSymbolAddress((void**)&hbl, g_hb_lo);
    cudaGetSymbolAddress((void**)&qkvh, g_qkvh);
    cudaGetSymbolAddress((void**)&wq, g_wqkv);
    cudaGetSymbolAddress((void**)&wp, g_wproj);
    cudaGetSymbolAddress((void**)&w1, g_wfc1);
    cudaGetSymbolAddress((void**)&w2, g_wfc2);
    cudaGetSymbolAddress((void**)&x1, g_x1);

    cudaFuncSetAttribute(gemm_mma<1>, cudaFuncAttributeMaxDynamicSharedMemorySize, GEMM_SMEM_BYTES);
    cudaFuncSetAttribute(gemm_mma<2>, cudaFuncAttributeMaxDynamicSharedMemorySize, GEMM_SMEM_BYTES);
    cudaFuncSetAttribute(gemm_mma<3>, cudaFuncAttributeMaxDynamicSharedMemorySize, GEMM_SMEM_BYTES);
    cudaFuncSetAttribute(attn_mma_kernel, cudaFuncAttributeMaxDynamicSharedMemorySize, ATTN_SMEM);

    const dim3 wblk(32, 8);
    const int MB = (NTOK + 127) / 128;  // 71

    // weight transpose + fp16 convert
    wconv_kernel<<<dim3(H3/32,  EMB/32),  wblk>>>(qkv_w,  EMB,  H3,   wq);
    wconv_kernel<<<dim3(EMB/32, EMB/32),  wblk>>>(proj_w, EMB,  EMB,  wp);
    wconv_kernel<<<dim3(FHID/32,EMB/32),  wblk>>>(fc1_w,  EMB,  FHID, w1);
    wconv_kernel<<<dim3(EMB/32, FHID/32), wblk>>>(fc2_w,  FHID, EMB,  w2);

    // 1. LN1 -> hi/lo
    ln_kernel<<<NTOK, 256>>>(x, ln1_g, ln1_b, xnh, xnl);
    // 2. QKV = xn @ qkv_w -> fp16
    gemm_mma<3><<<dim3(H3/128, MB), 256, GEMM_SMEM_BYTES>>>(
        xnh, xnl, EMB, wq, EMB, nullptr, H3, NTOK, nullptr, nullptr, 0, qkvh, nullptr);
    // 3. tensor-core flash attention -> ao hi/lo
    attn_mma_kernel<<<dim3(18, BATCH * NHEAD), 128, ATTN_SMEM>>>(qkvh, mask, aoh, aol);
    // 4. x1 = ao @ proj_w + b + x
    gemm_mma<1><<<dim3(EMB/128, MB), 256, GEMM_SMEM_BYTES>>>(
        aoh, aol, EMB, wp, EMB, x1, EMB, NTOK, proj_b, x, EMB, nullptr, nullptr);
    // 5. LN2 -> hi/lo
    ln_kernel<<<NTOK, 256>>>(x1, ln2_g, ln2_b, xnh, xnl);
    // 6. hb = gelu(xn @ fc1_w + b) -> hi/lo
    gemm_mma<2><<<dim3(FHID/128, MB), 256, GEMM_SMEM_BYTES>>>(
        xnh, xnl, EMB, w1, EMB, nullptr, FHID, NTOK, fc1_b, nullptr, 0, hbh, hbl);
    // 7. out = hb @ fc2_w + b + x1
    gemm_mma<1><<<dim3(EMB/128, MB), 256, GEMM_SMEM_BYTES>>>(
        hbh, hbl, FHID, w2, FHID, out, EMB, NTOK, fc2_b, x1, EMB, nullptr, nullptr);
}